// round 11
// baseline (speedup 1.0000x reference)
#include <cuda_runtime.h>
#include <cuda_bf16.h>
#include <cstdint>

// ---------------------------------------------------------------------------
// LinearMessagePassingLayer — GB300 sm_103a, round 11.
//   prep:  Wf fuse + fragment packing (1 kernel)
//   csr:   persistent kernel (software grid barrier)
//   node:  fused EVERYTHING: CSR gather (pull) + 3-GEMM MLP + 3 LayerNorms.
//          M=64 tiles, 256 thr, 2 blocks/SM. g_agg eliminated (-128MB traffic).
//   GEMMs: mma.sync m16n8k16 bf16, 3-term hi/lo split (~6e-6 rel err).
// ---------------------------------------------------------------------------

#define N_NODES 100000
#define N_EDGES 800000
#define D       128
#define ED      32
#define AD      160
#define LN_EPS  1e-5f
#define NB_SCAN ((N_NODES + 255) / 256)   // 391

#define KS1   18
#define KP1   296
#define KS2   8
#define MROWS 64
#define NGRP  ((N_NODES + MROWS - 1) / MROWS)   // 1563
#define CSRB  128

// --------------------------- device scratch -------------------------------
__device__ uint4    g_w1p[KS1 * 16 * 32];
__device__ uint4    g_w2p[KS2 * 16 * 32];
__device__ uint4    g_wnp[KS2 * 16 * 32];
__device__ int      g_sr[2 * N_EDGES];
__device__ int      g_cnt[N_NODES];
__device__ int      g_off[N_NODES + 1];
__device__ int      g_sid[N_EDGES];
__device__ int      g_eix[N_EDGES];
__device__ int      g_bsum[NB_SCAN];
__device__ int      g_boff[NB_SCAN];
__device__ unsigned g_bar;

// --------------------------- helpers ---------------------------------------
__device__ __forceinline__ uint16_t f2bf(float x) {
    __nv_bfloat16 h = __float2bfloat16(x);
    return *reinterpret_cast<uint16_t*>(&h);
}
__device__ __forceinline__ float bf2f(uint16_t b) {
    __nv_bfloat16 h = *reinterpret_cast<__nv_bfloat16*>(&b);
    return __bfloat162float(h);
}

__device__ __forceinline__ uint32_t smem_u32(const void* p) {
    uint32_t a;
    asm("{ .reg .u64 t; cvta.to.shared.u64 t, %1; cvt.u32.u64 %0, t; }"
        : "=r"(a) : "l"(p));
    return a;
}

__device__ __forceinline__ void mma_bf16(float (&c)[4], const uint32_t (&a)[4],
                                         uint32_t b0, uint32_t b1) {
    asm volatile(
        "mma.sync.aligned.m16n8k16.row.col.f32.bf16.bf16.f32 "
        "{%0,%1,%2,%3},{%4,%5,%6,%7},{%8,%9},{%0,%1,%2,%3};\n"
        : "+f"(c[0]), "+f"(c[1]), "+f"(c[2]), "+f"(c[3])
        : "r"(a[0]), "r"(a[1]), "r"(a[2]), "r"(a[3]), "r"(b0), "r"(b1));
}

__device__ __forceinline__ void ldsm_x4(uint32_t (&a)[4], uint32_t addr) {
    asm volatile("ldmatrix.sync.aligned.m8n8.x4.shared.b16 {%0,%1,%2,%3}, [%4];"
                 : "=r"(a[0]), "=r"(a[1]), "=r"(a[2]), "=r"(a[3]) : "r"(addr));
}

__device__ __forceinline__ void cvt_store(uint16_t* hi, uint16_t* lo, int off, float4 v) {
    uint16_t h0 = f2bf(v.x), h1 = f2bf(v.y), h2 = f2bf(v.z), h3 = f2bf(v.w);
    uint16_t l0 = f2bf(v.x - bf2f(h0)), l1 = f2bf(v.y - bf2f(h1));
    uint16_t l2 = f2bf(v.z - bf2f(h2)), l3 = f2bf(v.w - bf2f(h3));
    *(uint32_t*)(hi + off)     = ((uint32_t)h1 << 16) | h0;
    *(uint32_t*)(hi + off + 2) = ((uint32_t)h3 << 16) | h2;
    *(uint32_t*)(lo + off)     = ((uint32_t)l1 << 16) | l0;
    *(uint32_t*)(lo + off + 2) = ((uint32_t)l3 << 16) | l2;
}

__device__ __forceinline__ void mma_step_lm(float (&acc)[2][4][4],
                                            uint32_t aHi0, uint32_t aHi1,
                                            uint32_t aLo0, uint32_t aLo1,
                                            const uint4 (&B)[4]) {
    uint32_t ah0[4], ah1[4], al0[4], al1[4];
    ldsm_x4(ah0, aHi0);
    ldsm_x4(ah1, aHi1);
    ldsm_x4(al0, aLo0);
    ldsm_x4(al1, aLo1);
#pragma unroll
    for (int nf = 0; nf < 4; nf++) {
        mma_bf16(acc[0][nf], ah0, B[nf].x, B[nf].y);
        mma_bf16(acc[0][nf], ah0, B[nf].z, B[nf].w);
        mma_bf16(acc[0][nf], al0, B[nf].x, B[nf].y);
        mma_bf16(acc[1][nf], ah1, B[nf].x, B[nf].y);
        mma_bf16(acc[1][nf], ah1, B[nf].z, B[nf].w);
        mma_bf16(acc[1][nf], al1, B[nf].x, B[nf].y);
    }
}

__device__ __forceinline__ void load_bp(const uint4* __restrict__ wp, int ks,
                                        int wn, int lane, uint4 (&B)[4]) {
#pragma unroll
    for (int nf = 0; nf < 4; nf++)
        B[nf] = __ldg(wp + ((size_t)ks * 16 + wn * 4 + nf) * 32 + lane);
}

__device__ __forceinline__ uint4 pack_frag(float v0, float v1, float v2, float v3) {
    uint16_t h0 = f2bf(v0), h1 = f2bf(v1), h2 = f2bf(v2), h3 = f2bf(v3);
    uint16_t l0 = f2bf(v0 - bf2f(h0)), l1 = f2bf(v1 - bf2f(h1));
    uint16_t l2 = f2bf(v2 - bf2f(h2)), l3 = f2bf(v3 - bf2f(h3));
    uint4 r;
    r.x = ((uint32_t)h1 << 16) | h0;
    r.y = ((uint32_t)h3 << 16) | h2;
    r.z = ((uint32_t)l1 << 16) | l0;
    r.w = ((uint32_t)l3 << 16) | l2;
    return r;
}

// --------------------------- prep (fuse + pack) ------------------------------
__global__ void __launch_bounds__(AD)
prep_kernel(const float* __restrict__ W1, const float* __restrict__ Wm,
            const float* __restrict__ W2, const float* __restrict__ Wn) {
    __shared__ float sw[D];
    __shared__ float swf[AD];
    const int j = blockIdx.x, c = threadIdx.x;
    if (j == 0 && c == 0) g_bar = 0u;       // reset csr grid barrier per replay
    if (c < D) sw[c] = W1[j * (2 * D) + D + c];
    __syncthreads();
    {
        float s = 0.f;
        #pragma unroll 8
        for (int k = 0; k < D; k++)
            s += sw[k] * __ldg(&Wm[k * AD + c]);
        swf[c] = s;
    }
    __syncthreads();

    const int ngrp = j >> 3, qr = j & 7;
    if (c < KS1 * 4) {
        int ks = c >> 2, qkq = c & 3;
        int lane = qr * 4 + qkq;
        int k0 = ks * 16 + 2 * qkq;
        float v[4];
        #pragma unroll
        for (int jj = 0; jj < 4; jj++) {
            int k = k0 + (jj >> 1) * 8 + (jj & 1);
            v[jj] = (k < D) ? W1[j * (2 * D) + k] : swf[k - D];
        }
        g_w1p[ks * 512 + ngrp * 32 + lane] = pack_frag(v[0], v[1], v[2], v[3]);
    } else if (c < KS1 * 4 + KS2 * 4) {
        int t = c - KS1 * 4;
        int ks = t >> 2, qkq = t & 3;
        int lane = qr * 4 + qkq;
        int k0 = ks * 16 + 2 * qkq;
        g_w2p[ks * 512 + ngrp * 32 + lane] =
            pack_frag(W2[j * D + k0], W2[j * D + k0 + 1],
                      W2[j * D + k0 + 8], W2[j * D + k0 + 9]);
    } else if (c < KS1 * 4 + 2 * KS2 * 4) {
        int t = c - KS1 * 4 - KS2 * 4;
        int ks = t >> 2, qkq = t & 3;
        int lane = qr * 4 + qkq;
        int k0 = ks * 16 + 2 * qkq;
        g_wnp[ks * 512 + ngrp * 32 + lane] =
            pack_frag(Wn[j * D + k0], Wn[j * D + k0 + 1],
                      Wn[j * D + k0 + 8], Wn[j * D + k0 + 9]);
    }
}

// --------------------------- CSR build (persistent) ------------------------
__device__ __forceinline__ void grid_bar(unsigned target) {
    __syncthreads();
    if (threadIdx.x == 0) {
        __threadfence();
        atomicAdd(&g_bar, 1u);
        while (*(volatile unsigned*)&g_bar < target) { }
        __threadfence();
    }
    __syncthreads();
}

__global__ void __launch_bounds__(256)
csr_build_kernel(const void* __restrict__ p) {
    __shared__ int s[256];
    __shared__ int sh_base;
    __shared__ int anynz;
    const int t   = threadIdx.x;
    const int gid = blockIdx.x * 256 + t;
    const int gs  = CSRB * 256;

    for (int i = gid; i < N_NODES; i += gs) g_cnt[i] = 0;
    grid_bar(1 * CSRB);

    if (t == 0) anynz = 0;
    __syncthreads();
    if (t < 64) {
        if (((const unsigned int*)p)[2 * t + 1] != 0u) atomicOr(&anynz, 1);
    }
    __syncthreads();
    const int is64 = (anynz == 0);
    for (int i = gid; i < 2 * N_EDGES; i += gs) {
        int v = is64 ? (int)((const long long*)p)[i] : ((const int*)p)[i];
        g_sr[i] = v;
        if (i >= N_EDGES) atomicAdd(&g_cnt[v], 1);
    }
    grid_bar(2 * CSRB);

    {
        int w = gid >> 5, lane = t & 31;
        if (w < NB_SCAN) {
            int sum = 0;
            int base = w * 256 + lane * 8;
            #pragma unroll
            for (int j = 0; j < 8; j++) {
                int idx = base + j;
                if (idx < N_NODES) sum += __ldcg(&g_cnt[idx]);
            }
            #pragma unroll
            for (int o = 16; o; o >>= 1) sum += __shfl_xor_sync(0xffffffffu, sum, o);
            if (lane == 0) g_bsum[w] = sum;
        }
    }
    grid_bar(3 * CSRB);

    if (blockIdx.x == 0) {
        int a = (2 * t < NB_SCAN)     ? __ldcg(&g_bsum[2 * t])     : 0;
        int b = (2 * t + 1 < NB_SCAN) ? __ldcg(&g_bsum[2 * t + 1]) : 0;
        int c = a + b;
        s[t] = c;
        __syncthreads();
        for (int o = 1; o < 256; o <<= 1) {
            int x = (t >= o) ? s[t - o] : 0;
            __syncthreads();
            s[t] += x;
            __syncthreads();
        }
        int excl = s[t] - c;
        if (2 * t < NB_SCAN)     g_boff[2 * t]     = excl;
        if (2 * t + 1 < NB_SCAN) g_boff[2 * t + 1] = excl + a;
    }
    grid_bar(4 * CSRB);

    for (int c = blockIdx.x; c < NB_SCAN; c += CSRB) {
        const int i = c * 256 + t;
        int v = (i < N_NODES) ? __ldcg(&g_cnt[i]) : 0;
        s[t] = v;
        if (t == 0) sh_base = __ldcg(&g_boff[c]);
        __syncthreads();
        for (int o = 1; o < 256; o <<= 1) {
            int x = (t >= o) ? s[t - o] : 0;
            __syncthreads();
            s[t] += x;
            __syncthreads();
        }
        if (i < N_NODES) {
            int off = sh_base + s[t] - v;
            g_off[i] = off;
            g_cnt[i] = off;
        }
        __syncthreads();
    }
    if (blockIdx.x == 0 && t == 0) g_off[N_NODES] = N_EDGES;
    grid_bar(5 * CSRB);

    for (int e = gid; e < N_EDGES; e += gs) {
        int r = __ldcg(&g_sr[N_EDGES + e]);
        int pos = atomicAdd(&g_cnt[r], 1);
        g_sid[pos] = __ldcg(&g_sr[e]);
        g_eix[pos] = e;
    }
}

// --------------------------- fused pull + node phase ------------------------
// M=64 tile, 256 thr, 2 blocks/SM. Each warp gathers+converts its 8 rows:
//   X row = [nodes[n] (128) | sum nodes[sender] (128) | sum edge_attr (32)]
__global__ void __launch_bounds__(256, 2)
node_phase_kernel(const float4* __restrict__ nodes4,
                  const float4* __restrict__ ea4,
                  const float* __restrict__ b1,
                  const float* __restrict__ g1,
                  const float* __restrict__ be1,
                  const float* __restrict__ b2,
                  const float* __restrict__ g2,
                  const float* __restrict__ be2,
                  const float* __restrict__ gf,
                  const float* __restrict__ bef,
                  float* __restrict__ out) {
    extern __shared__ uint16_t smu[];
    uint16_t* sAhi = smu;
    uint16_t* sAlo = smu + MROWS * KP1;

    __shared__ float sb1[D], sg1[D], sbe1[D];
    __shared__ float sb2[D], sg2[D], sbe2[D], sgf[D], sbef[D];
    __shared__ float sredS[MROWS][4], sredQ[MROWS][4];

    const int tid = threadIdx.x;
    const int n0 = blockIdx.x * MROWS;
    if (tid < D) {
        sb1[tid] = b1[tid]; sg1[tid] = g1[tid]; sbe1[tid] = be1[tid];
        sb2[tid] = b2[tid]; sg2[tid] = g2[tid]; sbe2[tid] = be2[tid];
        sgf[tid] = gf[tid]; sbef[tid] = bef[tid];
    }

    const int lane = tid & 31;
    const int wid  = tid >> 5;        // 0..7

    // ---- fused CSR pull + convert: warp wid fills rows wid*8 .. wid*8+7 ----
    #pragma unroll 1
    for (int rr = 0; rr < 8; rr++) {
        const int row = wid * 8 + rr;
        const int node = n0 + row;
        float4 nv = make_float4(0.f, 0.f, 0.f, 0.f);
        float4 an = make_float4(0.f, 0.f, 0.f, 0.f);
        float4 ae = make_float4(0.f, 0.f, 0.f, 0.f);
        if (node < N_NODES) {
            nv = __ldg(nodes4 + (size_t)node * 32 + lane);
            const int beg = g_off[node], end = g_off[node + 1];
            int i = beg;
            for (; i + 4 <= end; i += 4) {
                int s0 = __ldg(&g_sid[i]),     s1 = __ldg(&g_sid[i + 1]);
                int s2 = __ldg(&g_sid[i + 2]), s3 = __ldg(&g_sid[i + 3]);
                float4 v0 = __ldg(nodes4 + (size_t)s0 * 32 + lane);
                float4 v1 = __ldg(nodes4 + (size_t)s1 * 32 + lane);
                float4 v2 = __ldg(nodes4 + (size_t)s2 * 32 + lane);
                float4 v3 = __ldg(nodes4 + (size_t)s3 * 32 + lane);
                an.x += v0.x + v1.x + v2.x + v3.x;
                an.y += v0.y + v1.y + v2.y + v3.y;
                an.z += v0.z + v1.z + v2.z + v3.z;
                an.w += v0.w + v1.w + v2.w + v3.w;
                if (lane < 8) {
                    int e0 = __ldg(&g_eix[i]),     e1 = __ldg(&g_eix[i + 1]);
                    int e2 = __ldg(&g_eix[i + 2]), e3 = __ldg(&g_eix[i + 3]);
                    float4 w0 = __ldg(ea4 + (size_t)e0 * 8 + lane);
                    float4 w1 = __ldg(ea4 + (size_t)e1 * 8 + lane);
                    float4 w2 = __ldg(ea4 + (size_t)e2 * 8 + lane);
                    float4 w3 = __ldg(ea4 + (size_t)e3 * 8 + lane);
                    ae.x += w0.x + w1.x + w2.x + w3.x;
                    ae.y += w0.y + w1.y + w2.y + w3.y;
                    ae.z += w0.z + w1.z + w2.z + w3.z;
                    ae.w += w0.w + w1.w + w2.w + w3.w;
                }
            }
            for (; i < end; i++) {
                int s = __ldg(&g_sid[i]);
                float4 v = __ldg(nodes4 + (size_t)s * 32 + lane);
                an.x += v.x; an.y += v.y; an.z += v.z; an.w += v.w;
                if (lane < 8) {
                    int e = __ldg(&g_eix[i]);
                    float4 w = __ldg(ea4 + (size_t)e * 8 + lane);
                    ae.x += w.x; ae.y += w.y; ae.z += w.z; ae.w += w.w;
                }
            }
        }
        cvt_store(sAhi, sAlo, row * KP1 + lane * 4, nv);
        cvt_store(sAhi, sAlo, row * KP1 + 128 + lane * 4, an);
        if (lane < 8)
            cvt_store(sAhi, sAlo, row * KP1 + 256 + lane * 4, ae);
    }
    __syncthreads();

    const int wm   = wid >> 2;        // 0..1 (32 rows each)
    const int wn   = wid & 3;         // 0..3 (32 cols each)
    const int qr   = lane >> 2;
    const int qk   = 2 * (lane & 3);
    const int nbase = wn * 32;

    const int mrow = ((lane >> 3) & 1) * 8 + (lane & 7);
    const int kof  = (lane >> 4) * 8;
    const uint32_t sbase = smem_u32(smu);
    const uint32_t aHi0 = sbase + ((wm * 32 + mrow) * KP1 + kof) * 2;
    const uint32_t aHi1 = aHi0 + 16 * KP1 * 2;
    const uint32_t aLo0 = aHi0 + MROWS * KP1 * 2;
    const uint32_t aLo1 = aHi1 + MROWS * KP1 * 2;

    const uint4* wp1 = (const uint4*)g_w1p;
    const uint4* wp2 = (const uint4*)g_w2p;
    const uint4* wpn = (const uint4*)g_wnp;
    uint4 B0[4], B1[4];

    // =================== GEMM 1: [nodes|agg] @ Wcat^T (K=288) ===============
    float acc[2][4][4];
    #pragma unroll
    for (int mf = 0; mf < 2; mf++)
        #pragma unroll
        for (int nf = 0; nf < 4; nf++)
            #pragma unroll
            for (int i = 0; i < 4; i++) acc[mf][nf][i] = 0.f;

    load_bp(wp1, 0, wn, lane, B0);
    #pragma unroll 1
    for (int ks = 0; ks < KS1; ks += 2) {
        load_bp(wp1, ks + 1, wn, lane, B1);
        mma_step_lm(acc, aHi0 + ks * 32, aHi1 + ks * 32,
                    aLo0 + ks * 32, aLo1 + ks * 32, B0);
        if (ks + 2 < KS1) load_bp(wp1, ks + 2, wn, lane, B0);
        mma_step_lm(acc, aHi0 + (ks + 1) * 32, aHi1 + (ks + 1) * 32,
                    aLo0 + (ks + 1) * 32, aLo1 + (ks + 1) * 32, B1);
    }

    load_bp(wp2, 0, wn, lane, B0);   // prefetch GEMM2 behind LN1 epilogue

    // ---- bias + relu ----
    float vals[2][4][4];
    #pragma unroll
    for (int mf = 0; mf < 2; mf++)
        #pragma unroll
        for (int nf = 0; nf < 4; nf++) {
            int c = nbase + nf * 8 + qk;
            vals[mf][nf][0] = fmaxf(acc[mf][nf][0] + sb1[c], 0.f);
            vals[mf][nf][1] = fmaxf(acc[mf][nf][1] + sb1[c + 1], 0.f);
            vals[mf][nf][2] = fmaxf(acc[mf][nf][2] + sb1[c], 0.f);
            vals[mf][nf][3] = fmaxf(acc[mf][nf][3] + sb1[c + 1], 0.f);
        }

    // ---- LN1 reductions ----
    #pragma unroll
    for (int mf = 0; mf < 2; mf++)
        #pragma unroll
        for (int h = 0; h < 2; h++) {
            float s = 0.f, q = 0.f;
            #pragma unroll
            for (int nf = 0; nf < 4; nf++) {
                float v0 = vals[mf][nf][2 * h], v1 = vals[mf][nf][2 * h + 1];
                s += v0 + v1; q += v0 * v0 + v1 * v1;
            }
            s += __shfl_xor_sync(0xffffffffu, s, 1);
            s += __shfl_xor_sync(0xffffffffu, s, 2);
            q += __shfl_xor_sync(0xffffffffu, q, 1);
            q += __shfl_xor_sync(0xffffffffu, q, 2);
            int r = wm * 32 + mf * 16 + h * 8 + qr;
            if ((lane & 3) == 0) { sredS[r][wn] = s; sredQ[r][wn] = q; }
        }
    __syncthreads();

    // ---- LN1 apply; write h into the agg columns of sA ----
    #pragma unroll
    for (int mf = 0; mf < 2; mf++)
        #pragma unroll
        for (int h = 0; h < 2; h++) {
            int r = wm * 32 + mf * 16 + h * 8 + qr;
            float S = sredS[r][0] + sredS[r][1] + sredS[r][2] + sredS[r][3];
            float Q = sredQ[r][0] + sredQ[r][1] + sredQ[r][2] + sredQ[r][3];
            float mu = S * (1.f / 128.f);
            float var = Q * (1.f / 128.f) - mu * mu;
            float rs = rsqrtf(var + LN_EPS);
            #pragma unroll
            for (int nf = 0; nf < 4; nf++) {
                int c = nbase + nf * 8 + qk;
                float y0 = (vals[mf][nf][2 * h] - mu) * rs * sg1[c] + sbe1[c];
                float y1 = (vals[mf][nf][2 * h + 1] - mu) * rs * sg1[c + 1] + sbe1[c + 1];
                uint16_t h0 = f2bf(y0), h1 = f2bf(y1);
                uint16_t l0 = f2bf(y0 - bf2f(h0)), l1 = f2bf(y1 - bf2f(h1));
                *(uint32_t*)(sAhi + r * KP1 + 128 + c) = ((uint32_t)h1 << 16) | h0;
                *(uint32_t*)(sAlo + r * KP1 + 128 + c) = ((uint32_t)l1 << 16) | l0;
            }
        }
    __syncthreads();

    // =================== GEMM 2: h @ W2^T (K=128) ===========================
    #pragma unroll
    for (int mf = 0; mf < 2; mf++)
        #pragma unroll
        for (int nf = 0; nf < 4; nf++)
            #pragma unroll
            for (int i = 0; i < 4; i++) acc[mf][nf][i] = 0.f;
    #pragma unroll 1
    for (int ks = 0; ks < KS2; ks += 2) {
        load_bp(wp2, ks + 1, wn, lane, B1);
        mma_step_lm(acc, aHi0 + 256 + ks * 32, aHi1 + 256 + ks * 32,
                    aLo0 + 256 + ks * 32, aLo1 + 256 + ks * 32, B0);
        if (ks + 2 < KS2) load_bp(wp2, ks + 2, wn, lane, B0);
        mma_step_lm(acc, aHi0 + 256 + (ks + 1) * 32, aHi1 + 256 + (ks + 1) * 32,
                    aLo0 + 256 + (ks + 1) * 32, aLo1 + 256 + (ks + 1) * 32, B1);
    }

    load_bp(wpn, 0, wn, lane, B0);   // prefetch GEMM3 behind LN2 epilogue

    // ---- bias + relu -> uvals ----
    float uvals[2][4][4];
    #pragma unroll
    for (int mf = 0; mf < 2; mf++)
        #pragma unroll
        for (int nf = 0; nf < 4; nf++) {
            int c = nbase + nf * 8 + qk;
            uvals[mf][nf][0] = fmaxf(acc[mf][nf][0] + sb2[c], 0.f);
            uvals[mf][nf][1] = fmaxf(acc[mf][nf][1] + sb2[c + 1], 0.f);
            uvals[mf][nf][2] = fmaxf(acc[mf][nf][2] + sb2[c], 0.f);
            uvals[mf][nf][3] = fmaxf(acc[mf][nf][3] + sb2[c + 1], 0.f);
        }

    // ---- LN2 ----
    __syncthreads();
    #pragma unroll
    for (int mf = 0; mf < 2; mf++)
        #pragma unroll
        for (int h = 0; h < 2; h++) {
            float s = 0.f, q = 0.f;
            #pragma unroll
            for (int nf = 0; nf < 4; nf++) {
                float v0 = uvals[mf][nf][2 * h], v1 = uvals[mf][nf][2 * h + 1];
                s += v0 + v1; q += v0 * v0 + v1 * v1;
            }
            s += __shfl_xor_sync(0xffffffffu, s, 1);
            s += __shfl_xor_sync(0xffffffffu, s, 2);
            q += __shfl_xor_sync(0xffffffffu, q, 1);
            q += __shfl_xor_sync(0xffffffffu, q, 2);
            int r = wm * 32 + mf * 16 + h * 8 + qr;
            if ((lane & 3) == 0) { sredS[r][wn] = s; sredQ[r][wn] = q; }
        }
    __syncthreads();

    #pragma unroll
    for (int mf = 0; mf < 2; mf++)
        #pragma unroll
        for (int h = 0; h < 2; h++) {
            int r = wm * 32 + mf * 16 + h * 8 + qr;
            float S = sredS[r][0] + sredS[r][1] + sredS[r][2] + sredS[r][3];
            float Q = sredQ[r][0] + sredQ[r][1] + sredQ[r][2] + sredQ[r][3];
            float mu = S * (1.f / 128.f);
            float var = Q * (1.f / 128.f) - mu * mu;
            float rs = rsqrtf(var + LN_EPS);
            #pragma unroll
            for (int nf = 0; nf < 4; nf++) {
                int c = nbase + nf * 8 + qk;
                uvals[mf][nf][2 * h]     = (uvals[mf][nf][2 * h] - mu) * rs * sg2[c] + sbe2[c];
                uvals[mf][nf][2 * h + 1] = (uvals[mf][nf][2 * h + 1] - mu) * rs * sg2[c + 1] + sbe2[c + 1];
            }
        }
    __syncthreads();

    // =================== GEMM 3: nodes @ Wn^T (K=128) =======================
    #pragma unroll
    for (int mf = 0; mf < 2; mf++)
        #pragma unroll
        for (int nf = 0; nf < 4; nf++)
            #pragma unroll
            for (int i = 0; i < 4; i++) acc[mf][nf][i] = 0.f;
    #pragma unroll 1
    for (int ks = 0; ks < KS2; ks += 2) {
        load_bp(wpn, ks + 1, wn, lane, B1);
        mma_step_lm(acc, aHi0 + ks * 32, aHi1 + ks * 32,
                    aLo0 + ks * 32, aLo1 + ks * 32, B0);
        if (ks + 2 < KS2) load_bp(wpn, ks + 2, wn, lane, B0);
        mma_step_lm(acc, aHi0 + (ks + 1) * 32, aHi1 + (ks + 1) * 32,
                    aLo0 + (ks + 1) * 32, aLo1 + (ks + 1) * 32, B1);
    }

    // ---- v = acc + u; final LN ----
    #pragma unroll
    for (int mf = 0; mf < 2; mf++)
        #pragma unroll
        for (int nf = 0; nf < 4; nf++)
            #pragma unroll
            for (int i = 0; i < 4; i++)
                uvals[mf][nf][i] += acc[mf][nf][i];

    #pragma unroll
    for (int mf = 0; mf < 2; mf++)
        #pragma unroll
        for (int h = 0; h < 2; h++) {
            float s = 0.f, q = 0.f;
            #pragma unroll
            for (int nf = 0; nf < 4; nf++) {
                float v0 = uvals[mf][nf][2 * h], v1 = uvals[mf][nf][2 * h + 1];
                s += v0 + v1; q += v0 * v0 + v1 * v1;
            }
            s += __shfl_xor_sync(0xffffffffu, s, 1);
            s += __shfl_xor_sync(0xffffffffu, s, 2);
            q += __shfl_xor_sync(0xffffffffu, q, 1);
            q += __shfl_xor_sync(0xffffffffu, q, 2);
            int r = wm * 32 + mf * 16 + h * 8 + qr;
            if ((lane & 3) == 0) { sredS[r][wn] = s; sredQ[r][wn] = q; }
        }
    __syncthreads();

    #pragma unroll
    for (int mf = 0; mf < 2; mf++)
        #pragma unroll
        for (int h = 0; h < 2; h++) {
            int r = wm * 32 + mf * 16 + h * 8 + qr;
            int node = n0 + r;
            if (node >= N_NODES) continue;
            float S = sredS[r][0] + sredS[r][1] + sredS[r][2] + sredS[r][3];
            float Q = sredQ[r][0] + sredQ[r][1] + sredQ[r][2] + sredQ[r][3];
            float mu = S * (1.f / 128.f);
            float var = Q * (1.f / 128.f) - mu * mu;
            float rs = rsqrtf(var + LN_EPS);
            #pragma unroll
            for (int nf = 0; nf < 4; nf++) {
                int c = nbase + nf * 8 + qk;
                float2 o;
                o.x = (uvals[mf][nf][2 * h] - mu) * rs * sgf[c] + sbef[c];
                o.y = (uvals[mf][nf][2 * h + 1] - mu) * rs * sgf[c + 1] + sbef[c + 1];
                *(float2*)(out + (size_t)node * D + c) = o;
            }
        }
}

// --------------------------- launch -----------------------------------------
extern "C" void kernel_launch(void* const* d_in, const int* in_sizes, int n_in,
                              void* d_out, int out_size) {
    const float* nodes     = (const float*)d_in[0];
    const void*  eidx      = d_in[1];
    const float* edge_attr = (const float*)d_in[2];
    const float* Wm        = (const float*)d_in[3];
    const float* Wn        = (const float*)d_in[4];
    const float* W1        = (const float*)d_in[5];
    const float* b1        = (const float*)d_in[6];
    const float* g1        = (const float*)d_in[7];
    const float* be1       = (const float*)d_in[8];
    const float* W2        = (const float*)d_in[9];
    const float* b2        = (const float*)d_in[10];
    const float* g2        = (const float*)d_in[11];
    const float* be2       = (const float*)d_in[12];
    const float* gf        = (const float*)d_in[13];
    const float* bef       = (const float*)d_in[14];
    float* out = (float*)d_out;

    const int smem = MROWS * KP1 * 2 * (int)sizeof(uint16_t);   // 75776
    cudaFuncSetAttribute(node_phase_kernel, cudaFuncAttributeMaxDynamicSharedMemorySize, smem);

    prep_kernel<<<D, AD>>>(W1, Wm, W2, Wn);                                  // 1 (+bar reset)
    csr_build_kernel<<<CSRB, 256>>>(eidx);                                   // 2
    node_phase_kernel<<<NGRP, 256, smem>>>(                                  // 3
        (const float4*)nodes, (const float4*)edge_attr,
        b1, g1, be1, b2, g2, be2, gf, bef, out);
}

// round 12
// speedup vs baseline: 1.1912x; 1.1912x over previous
#include <cuda_runtime.h>
#include <cuda_bf16.h>
#include <cstdint>

// ---------------------------------------------------------------------------
// LinearMessagePassingLayer — GB300 sm_103a, round 12.
//   csr:   persistent kernel; phase P0 ALSO does weight fuse+pack (prep folded)
//   pull:  CSR gather-sum (x4 unroll)   [~78us, DRAM floor]
//   node:  fused MLP, M=64 tiles, 256 thr, 2 blocks/SM (round-8 structure)
//   GEMMs: mma.sync m16n8k16 bf16, 3-term hi/lo split (~6e-6 rel err).
// ---------------------------------------------------------------------------

#define N_NODES 100000
#define N_EDGES 800000
#define D       128
#define ED      32
#define AD      160
#define LN_EPS  1e-5f
#define NB_SCAN ((N_NODES + 255) / 256)   // 391

#define KS1   18
#define KP1   296
#define KS2   8
#define MROWS 64
#define NGRP  ((N_NODES + MROWS - 1) / MROWS)   // 1563
#define CSRB  148

// --------------------------- device scratch -------------------------------
__device__ uint4    g_w1p[KS1 * 16 * 32];
__device__ uint4    g_w2p[KS2 * 16 * 32];
__device__ uint4    g_wnp[KS2 * 16 * 32];
__device__ float    g_agg[(size_t)N_NODES * AD];
__device__ int      g_sr[2 * N_EDGES];
__device__ int      g_cnt[N_NODES];
__device__ int      g_off[N_NODES + 1];
__device__ int      g_sid[N_EDGES];
__device__ int      g_eix[N_EDGES];
__device__ int      g_bsum[NB_SCAN];
__device__ int      g_boff[NB_SCAN];
__device__ unsigned g_bar;

// --------------------------- helpers ---------------------------------------
__device__ __forceinline__ uint16_t f2bf(float x) {
    __nv_bfloat16 h = __float2bfloat16(x);
    return *reinterpret_cast<uint16_t*>(&h);
}
__device__ __forceinline__ float bf2f(uint16_t b) {
    __nv_bfloat16 h = *reinterpret_cast<__nv_bfloat16*>(&b);
    return __bfloat162float(h);
}

__device__ __forceinline__ uint32_t smem_u32(const void* p) {
    uint32_t a;
    asm("{ .reg .u64 t; cvta.to.shared.u64 t, %1; cvt.u32.u64 %0, t; }"
        : "=r"(a) : "l"(p));
    return a;
}

__device__ __forceinline__ void mma_bf16(float (&c)[4], const uint32_t (&a)[4],
                                         uint32_t b0, uint32_t b1) {
    asm volatile(
        "mma.sync.aligned.m16n8k16.row.col.f32.bf16.bf16.f32 "
        "{%0,%1,%2,%3},{%4,%5,%6,%7},{%8,%9},{%0,%1,%2,%3};\n"
        : "+f"(c[0]), "+f"(c[1]), "+f"(c[2]), "+f"(c[3])
        : "r"(a[0]), "r"(a[1]), "r"(a[2]), "r"(a[3]), "r"(b0), "r"(b1));
}

__device__ __forceinline__ void ldsm_x4(uint32_t (&a)[4], uint32_t addr) {
    asm volatile("ldmatrix.sync.aligned.m8n8.x4.shared.b16 {%0,%1,%2,%3}, [%4];"
                 : "=r"(a[0]), "=r"(a[1]), "=r"(a[2]), "=r"(a[3]) : "r"(addr));
}

__device__ __forceinline__ void cvt_store(uint16_t* hi, uint16_t* lo, int off, float4 v) {
    uint16_t h0 = f2bf(v.x), h1 = f2bf(v.y), h2 = f2bf(v.z), h3 = f2bf(v.w);
    uint16_t l0 = f2bf(v.x - bf2f(h0)), l1 = f2bf(v.y - bf2f(h1));
    uint16_t l2 = f2bf(v.z - bf2f(h2)), l3 = f2bf(v.w - bf2f(h3));
    *(uint32_t*)(hi + off)     = ((uint32_t)h1 << 16) | h0;
    *(uint32_t*)(hi + off + 2) = ((uint32_t)h3 << 16) | h2;
    *(uint32_t*)(lo + off)     = ((uint32_t)l1 << 16) | l0;
    *(uint32_t*)(lo + off + 2) = ((uint32_t)l3 << 16) | l2;
}

__device__ __forceinline__ void mma_step_lm(float (&acc)[2][4][4],
                                            uint32_t aHi0, uint32_t aHi1,
                                            uint32_t aLo0, uint32_t aLo1,
                                            const uint4 (&B)[4]) {
    uint32_t ah0[4], ah1[4], al0[4], al1[4];
    ldsm_x4(ah0, aHi0);
    ldsm_x4(ah1, aHi1);
    ldsm_x4(al0, aLo0);
    ldsm_x4(al1, aLo1);
#pragma unroll
    for (int nf = 0; nf < 4; nf++) {
        mma_bf16(acc[0][nf], ah0, B[nf].x, B[nf].y);
        mma_bf16(acc[0][nf], ah0, B[nf].z, B[nf].w);
        mma_bf16(acc[0][nf], al0, B[nf].x, B[nf].y);
        mma_bf16(acc[1][nf], ah1, B[nf].x, B[nf].y);
        mma_bf16(acc[1][nf], ah1, B[nf].z, B[nf].w);
        mma_bf16(acc[1][nf], al1, B[nf].x, B[nf].y);
    }
}

__device__ __forceinline__ void load_bp(const uint4* __restrict__ wp, int ks,
                                        int wn, int lane, uint4 (&B)[4]) {
#pragma unroll
    for (int nf = 0; nf < 4; nf++)
        B[nf] = __ldg(wp + ((size_t)ks * 16 + wn * 4 + nf) * 32 + lane);
}

__device__ __forceinline__ uint4 pack_frag(float v0, float v1, float v2, float v3) {
    uint16_t h0 = f2bf(v0), h1 = f2bf(v1), h2 = f2bf(v2), h3 = f2bf(v3);
    uint16_t l0 = f2bf(v0 - bf2f(h0)), l1 = f2bf(v1 - bf2f(h1));
    uint16_t l2 = f2bf(v2 - bf2f(h2)), l3 = f2bf(v3 - bf2f(h3));
    uint4 r;
    r.x = ((uint32_t)h1 << 16) | h0;
    r.y = ((uint32_t)h3 << 16) | h2;
    r.z = ((uint32_t)l1 << 16) | l0;
    r.w = ((uint32_t)l3 << 16) | l2;
    return r;
}

// --------------------------- CSR build + weight prep (persistent) ----------
__device__ __forceinline__ void grid_bar(unsigned target) {
    __syncthreads();
    if (threadIdx.x == 0) {
        __threadfence();
        atomicAdd(&g_bar, 1u);
        while (*(volatile unsigned*)&g_bar < target) { }
        __threadfence();
    }
    __syncthreads();
}

__global__ void __launch_bounds__(256)
csr_build_kernel(const void* __restrict__ p,
                 const float* __restrict__ W1, const float* __restrict__ Wm,
                 const float* __restrict__ W2, const float* __restrict__ Wn) {
    __shared__ int s[256];
    __shared__ int sh_base;
    __shared__ int anynz;
    __shared__ float sw[D];
    __shared__ float swf[AD];
    const int t   = threadIdx.x;
    const int gid = blockIdx.x * 256 + t;
    const int gs  = CSRB * 256;

    // ---- P0: zero counts + (blocks < 128) weight fuse + pack ----
    for (int i = gid; i < N_NODES; i += gs) g_cnt[i] = 0;
    if (blockIdx.x < D) {
        const int j = blockIdx.x;
        if (t < D) sw[t] = W1[j * (2 * D) + D + t];
        __syncthreads();
        if (t < AD) {
            float acc = 0.f;
            #pragma unroll 8
            for (int k = 0; k < D; k++)
                acc += sw[k] * __ldg(&Wm[k * AD + t]);
            swf[t] = acc;
        }
        __syncthreads();
        const int ngrp = j >> 3, qr = j & 7;
        if (t < KS1 * 4) {
            int ks = t >> 2, qkq = t & 3;
            int lane = qr * 4 + qkq;
            int k0 = ks * 16 + 2 * qkq;
            float v[4];
            #pragma unroll
            for (int jj = 0; jj < 4; jj++) {
                int k = k0 + (jj >> 1) * 8 + (jj & 1);
                v[jj] = (k < D) ? W1[j * (2 * D) + k] : swf[k - D];
            }
            g_w1p[ks * 512 + ngrp * 32 + lane] = pack_frag(v[0], v[1], v[2], v[3]);
        } else if (t < KS1 * 4 + KS2 * 4) {
            int tt = t - KS1 * 4;
            int ks = tt >> 2, qkq = tt & 3;
            int lane = qr * 4 + qkq;
            int k0 = ks * 16 + 2 * qkq;
            g_w2p[ks * 512 + ngrp * 32 + lane] =
                pack_frag(W2[j * D + k0], W2[j * D + k0 + 1],
                          W2[j * D + k0 + 8], W2[j * D + k0 + 9]);
        } else if (t < KS1 * 4 + 2 * KS2 * 4) {
            int tt = t - KS1 * 4 - KS2 * 4;
            int ks = tt >> 2, qkq = tt & 3;
            int lane = qr * 4 + qkq;
            int k0 = ks * 16 + 2 * qkq;
            g_wnp[ks * 512 + ngrp * 32 + lane] =
                pack_frag(Wn[j * D + k0], Wn[j * D + k0 + 1],
                          Wn[j * D + k0 + 8], Wn[j * D + k0 + 9]);
        }
    }
    grid_bar(1 * CSRB);

    // ---- P1: convert indices + histogram receivers ----
    if (t == 0) anynz = 0;
    __syncthreads();
    if (t < 64) {
        if (((const unsigned int*)p)[2 * t + 1] != 0u) atomicOr(&anynz, 1);
    }
    __syncthreads();
    const int is64 = (anynz == 0);
    for (int i = gid; i < 2 * N_EDGES; i += gs) {
        int v = is64 ? (int)((const long long*)p)[i] : ((const int*)p)[i];
        g_sr[i] = v;
        if (i >= N_EDGES) atomicAdd(&g_cnt[v], 1);
    }
    grid_bar(2 * CSRB);

    // ---- P2: per-chunk sums ----
    {
        int w = gid >> 5, lane = t & 31;
        if (w < NB_SCAN) {
            int sum = 0;
            int base = w * 256 + lane * 8;
            #pragma unroll
            for (int j = 0; j < 8; j++) {
                int idx = base + j;
                if (idx < N_NODES) sum += __ldcg(&g_cnt[idx]);
            }
            #pragma unroll
            for (int o = 16; o; o >>= 1) sum += __shfl_xor_sync(0xffffffffu, sum, o);
            if (lane == 0) g_bsum[w] = sum;
        }
    }
    grid_bar(3 * CSRB);

    // ---- P3: scan chunk sums (block 0) ----
    if (blockIdx.x == 0) {
        int a = (2 * t < NB_SCAN)     ? __ldcg(&g_bsum[2 * t])     : 0;
        int b = (2 * t + 1 < NB_SCAN) ? __ldcg(&g_bsum[2 * t + 1]) : 0;
        int c = a + b;
        s[t] = c;
        __syncthreads();
        for (int o = 1; o < 256; o <<= 1) {
            int x = (t >= o) ? s[t - o] : 0;
            __syncthreads();
            s[t] += x;
            __syncthreads();
        }
        int excl = s[t] - c;
        if (2 * t < NB_SCAN)     g_boff[2 * t]     = excl;
        if (2 * t + 1 < NB_SCAN) g_boff[2 * t + 1] = excl + a;
    }
    grid_bar(4 * CSRB);

    // ---- P4: scatter offsets ----
    for (int c = blockIdx.x; c < NB_SCAN; c += CSRB) {
        const int i = c * 256 + t;
        int v = (i < N_NODES) ? __ldcg(&g_cnt[i]) : 0;
        s[t] = v;
        if (t == 0) sh_base = __ldcg(&g_boff[c]);
        __syncthreads();
        for (int o = 1; o < 256; o <<= 1) {
            int x = (t >= o) ? s[t - o] : 0;
            __syncthreads();
            s[t] += x;
            __syncthreads();
        }
        if (i < N_NODES) {
            int off = sh_base + s[t] - v;
            g_off[i] = off;
            g_cnt[i] = off;
        }
        __syncthreads();
    }
    if (blockIdx.x == 0 && t == 0) g_off[N_NODES] = N_EDGES;
    grid_bar(5 * CSRB);

    // ---- P5: fill ----
    for (int e = gid; e < N_EDGES; e += gs) {
        int r = __ldcg(&g_sr[N_EDGES + e]);
        int pos = atomicAdd(&g_cnt[r], 1);
        g_sid[pos] = __ldcg(&g_sr[e]);
        g_eix[pos] = e;
    }
}

// --------------------------- pull aggregation -------------------------------
__global__ void __launch_bounds__(256)
pull_kernel(const float4* __restrict__ nodes4, const float4* __restrict__ ea4) {
    int n = blockIdx.x * 8 + (threadIdx.x >> 5);
    if (n >= N_NODES) return;
    const int lane = threadIdx.x & 31;
    const int beg = g_off[n], end = g_off[n + 1];
    float4 an = make_float4(0.f, 0.f, 0.f, 0.f);
    float4 ae = make_float4(0.f, 0.f, 0.f, 0.f);
    int i = beg;
    for (; i + 4 <= end; i += 4) {
        int s0 = __ldg(&g_sid[i]),     s1 = __ldg(&g_sid[i + 1]);
        int s2 = __ldg(&g_sid[i + 2]), s3 = __ldg(&g_sid[i + 3]);
        float4 v0 = __ldg(nodes4 + (size_t)s0 * 32 + lane);
        float4 v1 = __ldg(nodes4 + (size_t)s1 * 32 + lane);
        float4 v2 = __ldg(nodes4 + (size_t)s2 * 32 + lane);
        float4 v3 = __ldg(nodes4 + (size_t)s3 * 32 + lane);
        an.x += v0.x + v1.x + v2.x + v3.x;
        an.y += v0.y + v1.y + v2.y + v3.y;
        an.z += v0.z + v1.z + v2.z + v3.z;
        an.w += v0.w + v1.w + v2.w + v3.w;
        if (lane < 8) {
            int e0 = __ldg(&g_eix[i]),     e1 = __ldg(&g_eix[i + 1]);
            int e2 = __ldg(&g_eix[i + 2]), e3 = __ldg(&g_eix[i + 3]);
            float4 w0 = __ldg(ea4 + (size_t)e0 * 8 + lane);
            float4 w1 = __ldg(ea4 + (size_t)e1 * 8 + lane);
            float4 w2 = __ldg(ea4 + (size_t)e2 * 8 + lane);
            float4 w3 = __ldg(ea4 + (size_t)e3 * 8 + lane);
            ae.x += w0.x + w1.x + w2.x + w3.x;
            ae.y += w0.y + w1.y + w2.y + w3.y;
            ae.z += w0.z + w1.z + w2.z + w3.z;
            ae.w += w0.w + w1.w + w2.w + w3.w;
        }
    }
    for (; i < end; i++) {
        int s = __ldg(&g_sid[i]);
        float4 v = __ldg(nodes4 + (size_t)s * 32 + lane);
        an.x += v.x; an.y += v.y; an.z += v.z; an.w += v.w;
        if (lane < 8) {
            int e = __ldg(&g_eix[i]);
            float4 w = __ldg(ea4 + (size_t)e * 8 + lane);
            ae.x += w.x; ae.y += w.y; ae.z += w.z; ae.w += w.w;
        }
    }
    float4* dst = reinterpret_cast<float4*>(g_agg) + (size_t)n * 40;
    dst[lane] = an;
    if (lane < 8) dst[32 + lane] = ae;
}

// --------------------------- fused node phase (M=64, 2 blk/SM) --------------
__global__ void __launch_bounds__(256, 2)
node_phase_kernel(const float* __restrict__ nodes,
                  const float* __restrict__ b1,
                  const float* __restrict__ g1,
                  const float* __restrict__ be1,
                  const float* __restrict__ b2,
                  const float* __restrict__ g2,
                  const float* __restrict__ be2,
                  const float* __restrict__ gf,
                  const float* __restrict__ bef,
                  float* __restrict__ out) {
    extern __shared__ uint16_t smu[];
    uint16_t* sAhi = smu;
    uint16_t* sAlo = smu + MROWS * KP1;

    __shared__ float sb1[D], sg1[D], sbe1[D];
    __shared__ float sb2[D], sg2[D], sbe2[D], sgf[D], sbef[D];
    __shared__ float sredS[MROWS][4], sredQ[MROWS][4];

    const int tid = threadIdx.x;
    const int n0 = blockIdx.x * MROWS;
    if (blockIdx.x == 0 && tid == 0) g_bar = 0u;   // reset csr grid barrier
    if (tid < D) {
        sb1[tid] = b1[tid]; sg1[tid] = g1[tid]; sbe1[tid] = be1[tid];
        sb2[tid] = b2[tid]; sg2[tid] = g2[tid]; sbe2[tid] = be2[tid];
        sgf[tid] = gf[tid]; sbef[tid] = bef[tid];
    }

    // ---- load + convert A = [nodes | agg] (64 rows) ----
    const float4* nsrc = (const float4*)nodes;
    #pragma unroll
    for (int it = 0; it < 8; it++) {
        int idx = it * 256 + tid;                 // 64*32 = 2048
        int row = idx >> 5, c4 = idx & 31;
        float4 v = make_float4(0.f, 0.f, 0.f, 0.f);
        if (n0 + row < N_NODES) v = __ldg(nsrc + (size_t)(n0 + row) * 32 + c4);
        cvt_store(sAhi, sAlo, row * KP1 + c4 * 4, v);
    }
    const float4* asrc = (const float4*)g_agg;
    #pragma unroll
    for (int it = 0; it < 10; it++) {
        int idx = it * 256 + tid;                 // 64*40 = 2560
        int row = idx / 40, c4 = idx % 40;
        float4 v = make_float4(0.f, 0.f, 0.f, 0.f);
        if (n0 + row < N_NODES) v = asrc[(size_t)(n0 + row) * 40 + c4];
        cvt_store(sAhi, sAlo, row * KP1 + 128 + c4 * 4, v);
    }
    __syncthreads();

    const int lane = tid & 31;
    const int wid  = tid >> 5;        // 0..7
    const int wm   = wid >> 2;        // 0..1 (32 rows each)
    const int wn   = wid & 3;         // 0..3 (32 cols each)
    const int qr   = lane >> 2;
    const int qk   = 2 * (lane & 3);
    const int nbase = wn * 32;

    const int mrow = ((lane >> 3) & 1) * 8 + (lane & 7);
    const int kof  = (lane >> 4) * 8;
    const uint32_t sbase = smem_u32(smu);
    const uint32_t aHi0 = sbase + ((wm * 32 + mrow) * KP1 + kof) * 2;
    const uint32_t aHi1 = aHi0 + 16 * KP1 * 2;
    const uint32_t aLo0 = aHi0 + MROWS * KP1 * 2;
    const uint32_t aLo1 = aHi1 + MROWS * KP1 * 2;

    const uint4* wp1 = (const uint4*)g_w1p;
    const uint4* wp2 = (const uint4*)g_w2p;
    const uint4* wpn = (const uint4*)g_wnp;
    uint4 B0[4], B1[4];

    // =================== GEMM 1: [nodes|agg] @ Wcat^T (K=288) ===============
    float acc[2][4][4];
    #pragma unroll
    for (int mf = 0; mf < 2; mf++)
        #pragma unroll
        for (int nf = 0; nf < 4; nf++)
            #pragma unroll
            for (int i = 0; i < 4; i++) acc[mf][nf][i] = 0.f;

    load_bp(wp1, 0, wn, lane, B0);
    #pragma unroll 1
    for (int ks = 0; ks < KS1; ks += 2) {
        load_bp(wp1, ks + 1, wn, lane, B1);
        mma_step_lm(acc, aHi0 + ks * 32, aHi1 + ks * 32,
                    aLo0 + ks * 32, aLo1 + ks * 32, B0);
        if (ks + 2 < KS1) load_bp(wp1, ks + 2, wn, lane, B0);
        mma_step_lm(acc, aHi0 + (ks + 1) * 32, aHi1 + (ks + 1) * 32,
                    aLo0 + (ks + 1) * 32, aLo1 + (ks + 1) * 32, B1);
    }

    load_bp(wp2, 0, wn, lane, B0);   // prefetch GEMM2 behind LN1 epilogue

    // ---- bias + relu ----
    float vals[2][4][4];
    #pragma unroll
    for (int mf = 0; mf < 2; mf++)
        #pragma unroll
        for (int nf = 0; nf < 4; nf++) {
            int c = nbase + nf * 8 + qk;
            vals[mf][nf][0] = fmaxf(acc[mf][nf][0] + sb1[c], 0.f);
            vals[mf][nf][1] = fmaxf(acc[mf][nf][1] + sb1[c + 1], 0.f);
            vals[mf][nf][2] = fmaxf(acc[mf][nf][2] + sb1[c], 0.f);
            vals[mf][nf][3] = fmaxf(acc[mf][nf][3] + sb1[c + 1], 0.f);
        }

    // ---- LN1 reductions ----
    #pragma unroll
    for (int mf = 0; mf < 2; mf++)
        #pragma unroll
        for (int h = 0; h < 2; h++) {
            float s = 0.f, q = 0.f;
            #pragma unroll
            for (int nf = 0; nf < 4; nf++) {
                float v0 = vals[mf][nf][2 * h], v1 = vals[mf][nf][2 * h + 1];
                s += v0 + v1; q += v0 * v0 + v1 * v1;
            }
            s += __shfl_xor_sync(0xffffffffu, s, 1);
            s += __shfl_xor_sync(0xffffffffu, s, 2);
            q += __shfl_xor_sync(0xffffffffu, q, 1);
            q += __shfl_xor_sync(0xffffffffu, q, 2);
            int r = wm * 32 + mf * 16 + h * 8 + qr;
            if ((lane & 3) == 0) { sredS[r][wn] = s; sredQ[r][wn] = q; }
        }
    __syncthreads();

    // ---- LN1 apply; write h into the agg columns of sA ----
    #pragma unroll
    for (int mf = 0; mf < 2; mf++)
        #pragma unroll
        for (int h = 0; h < 2; h++) {
            int r = wm * 32 + mf * 16 + h * 8 + qr;
            float S = sredS[r][0] + sredS[r][1] + sredS[r][2] + sredS[r][3];
            float Q = sredQ[r][0] + sredQ[r][1] + sredQ[r][2] + sredQ[r][3];
            float mu = S * (1.f / 128.f);
            float var = Q * (1.f / 128.f) - mu * mu;
            float rs = rsqrtf(var + LN_EPS);
            #pragma unroll
            for (int nf = 0; nf < 4; nf++) {
                int c = nbase + nf * 8 + qk;
                float y0 = (vals[mf][nf][2 * h] - mu) * rs * sg1[c] + sbe1[c];
                float y1 = (vals[mf][nf][2 * h + 1] - mu) * rs * sg1[c + 1] + sbe1[c + 1];
                uint16_t h0 = f2bf(y0), h1 = f2bf(y1);
                uint16_t l0 = f2bf(y0 - bf2f(h0)), l1 = f2bf(y1 - bf2f(h1));
                *(uint32_t*)(sAhi + r * KP1 + 128 + c) = ((uint32_t)h1 << 16) | h0;
                *(uint32_t*)(sAlo + r * KP1 + 128 + c) = ((uint32_t)l1 << 16) | l0;
            }
        }
    __syncthreads();

    // =================== GEMM 2: h @ W2^T (K=128) ===========================
    #pragma unroll
    for (int mf = 0; mf < 2; mf++)
        #pragma unroll
        for (int nf = 0; nf < 4; nf++)
            #pragma unroll
            for (int i = 0; i < 4; i++) acc[mf][nf][i] = 0.f;
    #pragma unroll 1
    for (int ks = 0; ks < KS2; ks += 2) {
        load_bp(wp2, ks + 1, wn, lane, B1);
        mma_step_lm(acc, aHi0 + 256 + ks * 32, aHi1 + 256 + ks * 32,
                    aLo0 + 256 + ks * 32, aLo1 + 256 + ks * 32, B0);
        if (ks + 2 < KS2) load_bp(wp2, ks + 2, wn, lane, B0);
        mma_step_lm(acc, aHi0 + 256 + (ks + 1) * 32, aHi1 + 256 + (ks + 1) * 32,
                    aLo0 + 256 + (ks + 1) * 32, aLo1 + 256 + (ks + 1) * 32, B1);
    }

    load_bp(wpn, 0, wn, lane, B0);   // prefetch GEMM3 behind LN2 epilogue

    // ---- bias + relu -> uvals ----
    float uvals[2][4][4];
    #pragma unroll
    for (int mf = 0; mf < 2; mf++)
        #pragma unroll
        for (int nf = 0; nf < 4; nf++) {
            int c = nbase + nf * 8 + qk;
            uvals[mf][nf][0] = fmaxf(acc[mf][nf][0] + sb2[c], 0.f);
            uvals[mf][nf][1] = fmaxf(acc[mf][nf][1] + sb2[c + 1], 0.f);
            uvals[mf][nf][2] = fmaxf(acc[mf][nf][2] + sb2[c], 0.f);
            uvals[mf][nf][3] = fmaxf(acc[mf][nf][3] + sb2[c + 1], 0.f);
        }

    // ---- LN2 ----
    __syncthreads();
    #pragma unroll
    for (int mf = 0; mf < 2; mf++)
        #pragma unroll
        for (int h = 0; h < 2; h++) {
            float s = 0.f, q = 0.f;
            #pragma unroll
            for (int nf = 0; nf < 4; nf++) {
                float v0 = uvals[mf][nf][2 * h], v1 = uvals[mf][nf][2 * h + 1];
                s += v0 + v1; q += v0 * v0 + v1 * v1;
            }
            s += __shfl_xor_sync(0xffffffffu, s, 1);
            s += __shfl_xor_sync(0xffffffffu, s, 2);
            q += __shfl_xor_sync(0xffffffffu, q, 1);
            q += __shfl_xor_sync(0xffffffffu, q, 2);
            int r = wm * 32 + mf * 16 + h * 8 + qr;
            if ((lane & 3) == 0) { sredS[r][wn] = s; sredQ[r][wn] = q; }
        }
    __syncthreads();

    #pragma unroll
    for (int mf = 0; mf < 2; mf++)
        #pragma unroll
        for (int h = 0; h < 2; h++) {
            int r = wm * 32 + mf * 16 + h * 8 + qr;
            float S = sredS[r][0] + sredS[r][1] + sredS[r][2] + sredS[r][3];
            float Q = sredQ[r][0] + sredQ[r][1] + sredQ[r][2] + sredQ[r][3];
            float mu = S * (1.f / 128.f);
            float var = Q * (1.f / 128.f) - mu * mu;
            float rs = rsqrtf(var + LN_EPS);
            #pragma unroll
            for (int nf = 0; nf < 4; nf++) {
                int c = nbase + nf * 8 + qk;
                uvals[mf][nf][2 * h]     = (uvals[mf][nf][2 * h] - mu) * rs * sg2[c] + sbe2[c];
                uvals[mf][nf][2 * h + 1] = (uvals[mf][nf][2 * h + 1] - mu) * rs * sg2[c + 1] + sbe2[c + 1];
            }
        }
    __syncthreads();

    // =================== GEMM 3: nodes @ Wn^T (K=128) =======================
    #pragma unroll
    for (int mf = 0; mf < 2; mf++)
        #pragma unroll
        for (int nf = 0; nf < 4; nf++)
            #pragma unroll
            for (int i = 0; i < 4; i++) acc[mf][nf][i] = 0.f;
    #pragma unroll 1
    for (int ks = 0; ks < KS2; ks += 2) {
        load_bp(wpn, ks + 1, wn, lane, B1);
        mma_step_lm(acc, aHi0 + ks * 32, aHi1 + ks * 32,
                    aLo0 + ks * 32, aLo1 + ks * 32, B0);
        if (ks + 2 < KS2) load_bp(wpn, ks + 2, wn, lane, B0);
        mma_step_lm(acc, aHi0 + (ks + 1) * 32, aHi1 + (ks + 1) * 32,
                    aLo0 + (ks + 1) * 32, aLo1 + (ks + 1) * 32, B1);
    }

    // ---- v = acc + u; final LN ----
    #pragma unroll
    for (int mf = 0; mf < 2; mf++)
        #pragma unroll
        for (int nf = 0; nf < 4; nf++)
            #pragma unroll
            for (int i = 0; i < 4; i++)
                uvals[mf][nf][i] += acc[mf][nf][i];

    #pragma unroll
    for (int mf = 0; mf < 2; mf++)
        #pragma unroll
        for (int h = 0; h < 2; h++) {
            float s = 0.f, q = 0.f;
            #pragma unroll
            for (int nf = 0; nf < 4; nf++) {
                float v0 = uvals[mf][nf][2 * h], v1 = uvals[mf][nf][2 * h + 1];
                s += v0 + v1; q += v0 * v0 + v1 * v1;
            }
            s += __shfl_xor_sync(0xffffffffu, s, 1);
            s += __shfl_xor_sync(0xffffffffu, s, 2);
            q += __shfl_xor_sync(0xffffffffu, q, 1);
            q += __shfl_xor_sync(0xffffffffu, q, 2);
            int r = wm * 32 + mf * 16 + h * 8 + qr;
            if ((lane & 3) == 0) { sredS[r][wn] = s; sredQ[r][wn] = q; }
        }
    __syncthreads();

    #pragma unroll
    for (int mf = 0; mf < 2; mf++)
        #pragma unroll
        for (int h = 0; h < 2; h++) {
            int r = wm * 32 + mf * 16 + h * 8 + qr;
            int node = n0 + r;
            if (node >= N_NODES) continue;
            float S = sredS[r][0] + sredS[r][1] + sredS[r][2] + sredS[r][3];
            float Q = sredQ[r][0] + sredQ[r][1] + sredQ[r][2] + sredQ[r][3];
            float mu = S * (1.f / 128.f);
            float var = Q * (1.f / 128.f) - mu * mu;
            float rs = rsqrtf(var + LN_EPS);
            #pragma unroll
            for (int nf = 0; nf < 4; nf++) {
                int c = nbase + nf * 8 + qk;
                float2 o;
                o.x = (uvals[mf][nf][2 * h] - mu) * rs * sgf[c] + sbef[c];
                o.y = (uvals[mf][nf][2 * h + 1] - mu) * rs * sgf[c + 1] + sbef[c + 1];
                *(float2*)(out + (size_t)node * D + c) = o;
            }
        }
}

// --------------------------- launch -----------------------------------------
extern "C" void kernel_launch(void* const* d_in, const int* in_sizes, int n_in,
                              void* d_out, int out_size) {
    const float* nodes     = (const float*)d_in[0];
    const void*  eidx      = d_in[1];
    const float* edge_attr = (const float*)d_in[2];
    const float* Wm        = (const float*)d_in[3];
    const float* Wn        = (const float*)d_in[4];
    const float* W1        = (const float*)d_in[5];
    const float* b1        = (const float*)d_in[6];
    const float* g1        = (const float*)d_in[7];
    const float* be1       = (const float*)d_in[8];
    const float* W2        = (const float*)d_in[9];
    const float* b2        = (const float*)d_in[10];
    const float* g2        = (const float*)d_in[11];
    const float* be2       = (const float*)d_in[12];
    const float* gf        = (const float*)d_in[13];
    const float* bef       = (const float*)d_in[14];
    float* out = (float*)d_out;

    const int smem = MROWS * KP1 * 2 * (int)sizeof(uint16_t);   // 75776
    cudaFuncSetAttribute(node_phase_kernel, cudaFuncAttributeMaxDynamicSharedMemorySize, smem);

    csr_build_kernel<<<CSRB, 256>>>(eidx, W1, Wm, W2, Wn);                   // 1
    pull_kernel<<<(N_NODES + 7) / 8, 256>>>(                                 // 2
        (const float4*)nodes, (const float4*)edge_attr);
    node_phase_kernel<<<NGRP, 256, smem>>>(nodes, b1, g1, be1,               // 3
                                           b2, g2, be2, gf, bef, out);
}

// round 13
// speedup vs baseline: 1.2104x; 1.0161x over previous
#include <cuda_runtime.h>
#include <cuda_bf16.h>
#include <cstdint>

// ---------------------------------------------------------------------------
// LinearMessagePassingLayer — GB300 sm_103a, round 13.
//   csr:   persistent kernel, CSRB=592 (4 blk/SM), vectorized convert+hist;
//          phase P0 also does weight fuse+pack
//   pull:  CSR gather-sum (x4 unroll)   [~78us, DRAM floor]
//   node:  fused MLP, M=64 tiles, 256 thr, 2 blocks/SM
//   GEMMs: mma.sync m16n8k16 bf16, 3-term hi/lo split (~6e-6 rel err).
// ---------------------------------------------------------------------------

#define N_NODES 100000
#define N_EDGES 800000
#define D       128
#define ED      32
#define AD      160
#define LN_EPS  1e-5f
#define NB_SCAN ((N_NODES + 255) / 256)   // 391

#define KS1   18
#define KP1   296
#define KS2   8
#define MROWS 64
#define NGRP  ((N_NODES + MROWS - 1) / MROWS)   // 1563
#define CSRB  592

// --------------------------- device scratch -------------------------------
__device__ uint4    g_w1p[KS1 * 16 * 32];
__device__ uint4    g_w2p[KS2 * 16 * 32];
__device__ uint4    g_wnp[KS2 * 16 * 32];
__device__ float    g_agg[(size_t)N_NODES * AD];
__device__ int      g_sr[2 * N_EDGES];
__device__ int      g_cnt[N_NODES];
__device__ int      g_off[N_NODES + 1];
__device__ int      g_sid[N_EDGES];
__device__ int      g_eix[N_EDGES];
__device__ int      g_bsum[NB_SCAN];
__device__ int      g_boff[NB_SCAN];
__device__ unsigned g_bar;

// --------------------------- helpers ---------------------------------------
__device__ __forceinline__ uint16_t f2bf(float x) {
    __nv_bfloat16 h = __float2bfloat16(x);
    return *reinterpret_cast<uint16_t*>(&h);
}
__device__ __forceinline__ float bf2f(uint16_t b) {
    __nv_bfloat16 h = *reinterpret_cast<__nv_bfloat16*>(&b);
    return __bfloat162float(h);
}

__device__ __forceinline__ uint32_t smem_u32(const void* p) {
    uint32_t a;
    asm("{ .reg .u64 t; cvta.to.shared.u64 t, %1; cvt.u32.u64 %0, t; }"
        : "=r"(a) : "l"(p));
    return a;
}

__device__ __forceinline__ void mma_bf16(float (&c)[4], const uint32_t (&a)[4],
                                         uint32_t b0, uint32_t b1) {
    asm volatile(
        "mma.sync.aligned.m16n8k16.row.col.f32.bf16.bf16.f32 "
        "{%0,%1,%2,%3},{%4,%5,%6,%7},{%8,%9},{%0,%1,%2,%3};\n"
        : "+f"(c[0]), "+f"(c[1]), "+f"(c[2]), "+f"(c[3])
        : "r"(a[0]), "r"(a[1]), "r"(a[2]), "r"(a[3]), "r"(b0), "r"(b1));
}

__device__ __forceinline__ void ldsm_x4(uint32_t (&a)[4], uint32_t addr) {
    asm volatile("ldmatrix.sync.aligned.m8n8.x4.shared.b16 {%0,%1,%2,%3}, [%4];"
                 : "=r"(a[0]), "=r"(a[1]), "=r"(a[2]), "=r"(a[3]) : "r"(addr));
}

__device__ __forceinline__ void cvt_store(uint16_t* hi, uint16_t* lo, int off, float4 v) {
    uint16_t h0 = f2bf(v.x), h1 = f2bf(v.y), h2 = f2bf(v.z), h3 = f2bf(v.w);
    uint16_t l0 = f2bf(v.x - bf2f(h0)), l1 = f2bf(v.y - bf2f(h1));
    uint16_t l2 = f2bf(v.z - bf2f(h2)), l3 = f2bf(v.w - bf2f(h3));
    *(uint32_t*)(hi + off)     = ((uint32_t)h1 << 16) | h0;
    *(uint32_t*)(hi + off + 2) = ((uint32_t)h3 << 16) | h2;
    *(uint32_t*)(lo + off)     = ((uint32_t)l1 << 16) | l0;
    *(uint32_t*)(lo + off + 2) = ((uint32_t)l3 << 16) | l2;
}

__device__ __forceinline__ void mma_step_lm(float (&acc)[2][4][4],
                                            uint32_t aHi0, uint32_t aHi1,
                                            uint32_t aLo0, uint32_t aLo1,
                                            const uint4 (&B)[4]) {
    uint32_t ah0[4], ah1[4], al0[4], al1[4];
    ldsm_x4(ah0, aHi0);
    ldsm_x4(ah1, aHi1);
    ldsm_x4(al0, aLo0);
    ldsm_x4(al1, aLo1);
#pragma unroll
    for (int nf = 0; nf < 4; nf++) {
        mma_bf16(acc[0][nf], ah0, B[nf].x, B[nf].y);
        mma_bf16(acc[0][nf], ah0, B[nf].z, B[nf].w);
        mma_bf16(acc[0][nf], al0, B[nf].x, B[nf].y);
        mma_bf16(acc[1][nf], ah1, B[nf].x, B[nf].y);
        mma_bf16(acc[1][nf], ah1, B[nf].z, B[nf].w);
        mma_bf16(acc[1][nf], al1, B[nf].x, B[nf].y);
    }
}

__device__ __forceinline__ void load_bp(const uint4* __restrict__ wp, int ks,
                                        int wn, int lane, uint4 (&B)[4]) {
#pragma unroll
    for (int nf = 0; nf < 4; nf++)
        B[nf] = __ldg(wp + ((size_t)ks * 16 + wn * 4 + nf) * 32 + lane);
}

__device__ __forceinline__ uint4 pack_frag(float v0, float v1, float v2, float v3) {
    uint16_t h0 = f2bf(v0), h1 = f2bf(v1), h2 = f2bf(v2), h3 = f2bf(v3);
    uint16_t l0 = f2bf(v0 - bf2f(h0)), l1 = f2bf(v1 - bf2f(h1));
    uint16_t l2 = f2bf(v2 - bf2f(h2)), l3 = f2bf(v3 - bf2f(h3));
    uint4 r;
    r.x = ((uint32_t)h1 << 16) | h0;
    r.y = ((uint32_t)h3 << 16) | h2;
    r.z = ((uint32_t)l1 << 16) | l0;
    r.w = ((uint32_t)l3 << 16) | l2;
    return r;
}

// --------------------------- CSR build + weight prep (persistent) ----------
__device__ __forceinline__ void grid_bar(unsigned target) {
    __syncthreads();
    if (threadIdx.x == 0) {
        __threadfence();
        atomicAdd(&g_bar, 1u);
        while (*(volatile unsigned*)&g_bar < target) { }
        __threadfence();
    }
    __syncthreads();
}

__global__ void __launch_bounds__(256)
csr_build_kernel(const void* __restrict__ p,
                 const float* __restrict__ W1, const float* __restrict__ Wm,
                 const float* __restrict__ W2, const float* __restrict__ Wn) {
    __shared__ int s[256];
    __shared__ int sh_base;
    __shared__ int anynz;
    __shared__ float sw[D];
    __shared__ float swf[AD];
    const int t   = threadIdx.x;
    const int gid = blockIdx.x * 256 + t;
    const int gs  = CSRB * 256;

    // ---- P0: zero counts + (blocks < 128) weight fuse + pack ----
    for (int i = gid; i < N_NODES; i += gs) g_cnt[i] = 0;
    if (blockIdx.x < D) {
        const int j = blockIdx.x;
        if (t < D) sw[t] = W1[j * (2 * D) + D + t];
        __syncthreads();
        if (t < AD) {
            float acc = 0.f;
            #pragma unroll 8
            for (int k = 0; k < D; k++)
                acc += sw[k] * __ldg(&Wm[k * AD + t]);
            swf[t] = acc;
        }
        __syncthreads();
        const int ngrp = j >> 3, qr = j & 7;
        if (t < KS1 * 4) {
            int ks = t >> 2, qkq = t & 3;
            int lane = qr * 4 + qkq;
            int k0 = ks * 16 + 2 * qkq;
            float v[4];
            #pragma unroll
            for (int jj = 0; jj < 4; jj++) {
                int k = k0 + (jj >> 1) * 8 + (jj & 1);
                v[jj] = (k < D) ? W1[j * (2 * D) + k] : swf[k - D];
            }
            g_w1p[ks * 512 + ngrp * 32 + lane] = pack_frag(v[0], v[1], v[2], v[3]);
        } else if (t < KS1 * 4 + KS2 * 4) {
            int tt = t - KS1 * 4;
            int ks = tt >> 2, qkq = tt & 3;
            int lane = qr * 4 + qkq;
            int k0 = ks * 16 + 2 * qkq;
            g_w2p[ks * 512 + ngrp * 32 + lane] =
                pack_frag(W2[j * D + k0], W2[j * D + k0 + 1],
                          W2[j * D + k0 + 8], W2[j * D + k0 + 9]);
        } else if (t < KS1 * 4 + 2 * KS2 * 4) {
            int tt = t - KS1 * 4 - KS2 * 4;
            int ks = tt >> 2, qkq = tt & 3;
            int lane = qr * 4 + qkq;
            int k0 = ks * 16 + 2 * qkq;
            g_wnp[ks * 512 + ngrp * 32 + lane] =
                pack_frag(Wn[j * D + k0], Wn[j * D + k0 + 1],
                          Wn[j * D + k0 + 8], Wn[j * D + k0 + 9]);
        }
    }
    grid_bar(1 * CSRB);

    // ---- P1: convert indices + histogram receivers (2x vectorized) ----
    if (t == 0) anynz = 0;
    __syncthreads();
    if (t < 64) {
        if (((const unsigned int*)p)[2 * t + 1] != 0u) atomicOr(&anynz, 1);
    }
    __syncthreads();
    const int is64 = (anynz == 0);
    for (int i0 = gid * 2; i0 < 2 * N_EDGES; i0 += gs * 2) {
        int v0, v1;
        if (is64) {
            longlong2 ll = __ldg((const longlong2*)((const char*)p + (size_t)i0 * 8));
            v0 = (int)ll.x; v1 = (int)ll.y;
        } else {
            int2 ii = __ldg((const int2*)((const char*)p + (size_t)i0 * 4));
            v0 = ii.x; v1 = ii.y;
        }
        g_sr[i0] = v0;
        g_sr[i0 + 1] = v1;
        if (i0 >= N_EDGES) {
            atomicAdd(&g_cnt[v0], 1);
            atomicAdd(&g_cnt[v1], 1);
        }
    }
    grid_bar(2 * CSRB);

    // ---- P2: per-chunk sums ----
    {
        int w = gid >> 5, lane = t & 31;
        if (w < NB_SCAN) {
            int sum = 0;
            int base = w * 256 + lane * 8;
            #pragma unroll
            for (int j = 0; j < 8; j++) {
                int idx = base + j;
                if (idx < N_NODES) sum += __ldcg(&g_cnt[idx]);
            }
            #pragma unroll
            for (int o = 16; o; o >>= 1) sum += __shfl_xor_sync(0xffffffffu, sum, o);
            if (lane == 0) g_bsum[w] = sum;
        }
    }
    grid_bar(3 * CSRB);

    // ---- P3: scan chunk sums (block 0) ----
    if (blockIdx.x == 0) {
        int a = (2 * t < NB_SCAN)     ? __ldcg(&g_bsum[2 * t])     : 0;
        int b = (2 * t + 1 < NB_SCAN) ? __ldcg(&g_bsum[2 * t + 1]) : 0;
        int c = a + b;
        s[t] = c;
        __syncthreads();
        for (int o = 1; o < 256; o <<= 1) {
            int x = (t >= o) ? s[t - o] : 0;
            __syncthreads();
            s[t] += x;
            __syncthreads();
        }
        int excl = s[t] - c;
        if (2 * t < NB_SCAN)     g_boff[2 * t]     = excl;
        if (2 * t + 1 < NB_SCAN) g_boff[2 * t + 1] = excl + a;
    }
    grid_bar(4 * CSRB);

    // ---- P4: scatter offsets ----
    for (int c = blockIdx.x; c < NB_SCAN; c += CSRB) {
        const int i = c * 256 + t;
        int v = (i < N_NODES) ? __ldcg(&g_cnt[i]) : 0;
        s[t] = v;
        if (t == 0) sh_base = __ldcg(&g_boff[c]);
        __syncthreads();
        for (int o = 1; o < 256; o <<= 1) {
            int x = (t >= o) ? s[t - o] : 0;
            __syncthreads();
            s[t] += x;
            __syncthreads();
        }
        if (i < N_NODES) {
            int off = sh_base + s[t] - v;
            g_off[i] = off;
            g_cnt[i] = off;
        }
        __syncthreads();
    }
    if (blockIdx.x == 0 && t == 0) g_off[N_NODES] = N_EDGES;
    grid_bar(5 * CSRB);

    // ---- P5: fill ----
    for (int e = gid; e < N_EDGES; e += gs) {
        int r = __ldcg(&g_sr[N_EDGES + e]);
        int pos = atomicAdd(&g_cnt[r], 1);
        g_sid[pos] = __ldcg(&g_sr[e]);
        g_eix[pos] = e;
    }
}

// --------------------------- pull aggregation -------------------------------
__global__ void __launch_bounds__(256)
pull_kernel(const float4* __restrict__ nodes4, const float4* __restrict__ ea4) {
    int n = blockIdx.x * 8 + (threadIdx.x >> 5);
    if (n >= N_NODES) return;
    const int lane = threadIdx.x & 31;
    const int beg = g_off[n], end = g_off[n + 1];
    float4 an = make_float4(0.f, 0.f, 0.f, 0.f);
    float4 ae = make_float4(0.f, 0.f, 0.f, 0.f);
    int i = beg;
    for (; i + 4 <= end; i += 4) {
        int s0 = __ldg(&g_sid[i]),     s1 = __ldg(&g_sid[i + 1]);
        int s2 = __ldg(&g_sid[i + 2]), s3 = __ldg(&g_sid[i + 3]);
        float4 v0 = __ldg(nodes4 + (size_t)s0 * 32 + lane);
        float4 v1 = __ldg(nodes4 + (size_t)s1 * 32 + lane);
        float4 v2 = __ldg(nodes4 + (size_t)s2 * 32 + lane);
        float4 v3 = __ldg(nodes4 + (size_t)s3 * 32 + lane);
        an.x += v0.x + v1.x + v2.x + v3.x;
        an.y += v0.y + v1.y + v2.y + v3.y;
        an.z += v0.z + v1.z + v2.z + v3.z;
        an.w += v0.w + v1.w + v2.w + v3.w;
        if (lane < 8) {
            int e0 = __ldg(&g_eix[i]),     e1 = __ldg(&g_eix[i + 1]);
            int e2 = __ldg(&g_eix[i + 2]), e3 = __ldg(&g_eix[i + 3]);
            float4 w0 = __ldg(ea4 + (size_t)e0 * 8 + lane);
            float4 w1 = __ldg(ea4 + (size_t)e1 * 8 + lane);
            float4 w2 = __ldg(ea4 + (size_t)e2 * 8 + lane);
            float4 w3 = __ldg(ea4 + (size_t)e3 * 8 + lane);
            ae.x += w0.x + w1.x + w2.x + w3.x;
            ae.y += w0.y + w1.y + w2.y + w3.y;
            ae.z += w0.z + w1.z + w2.z + w3.z;
            ae.w += w0.w + w1.w + w2.w + w3.w;
        }
    }
    for (; i < end; i++) {
        int s = __ldg(&g_sid[i]);
        float4 v = __ldg(nodes4 + (size_t)s * 32 + lane);
        an.x += v.x; an.y += v.y; an.z += v.z; an.w += v.w;
        if (lane < 8) {
            int e = __ldg(&g_eix[i]);
            float4 w = __ldg(ea4 + (size_t)e * 8 + lane);
            ae.x += w.x; ae.y += w.y; ae.z += w.z; ae.w += w.w;
        }
    }
    float4* dst = reinterpret_cast<float4*>(g_agg) + (size_t)n * 40;
    dst[lane] = an;
    if (lane < 8) dst[32 + lane] = ae;
}

// --------------------------- fused node phase (M=64, 2 blk/SM) --------------
__global__ void __launch_bounds__(256, 2)
node_phase_kernel(const float* __restrict__ nodes,
                  const float* __restrict__ b1,
                  const float* __restrict__ g1,
                  const float* __restrict__ be1,
                  const float* __restrict__ b2,
                  const float* __restrict__ g2,
                  const float* __restrict__ be2,
                  const float* __restrict__ gf,
                  const float* __restrict__ bef,
                  float* __restrict__ out) {
    extern __shared__ uint16_t smu[];
    uint16_t* sAhi = smu;
    uint16_t* sAlo = smu + MROWS * KP1;

    __shared__ float sb1[D], sg1[D], sbe1[D];
    __shared__ float sb2[D], sg2[D], sbe2[D], sgf[D], sbef[D];
    __shared__ float sredS[MROWS][4], sredQ[MROWS][4];

    const int tid = threadIdx.x;
    const int n0 = blockIdx.x * MROWS;
    if (blockIdx.x == 0 && tid == 0) g_bar = 0u;   // reset csr grid barrier
    if (tid < D) {
        sb1[tid] = b1[tid]; sg1[tid] = g1[tid]; sbe1[tid] = be1[tid];
        sb2[tid] = b2[tid]; sg2[tid] = g2[tid]; sbe2[tid] = be2[tid];
        sgf[tid] = gf[tid]; sbef[tid] = bef[tid];
    }

    // ---- load + convert A = [nodes | agg] (64 rows) ----
    const float4* nsrc = (const float4*)nodes;
    #pragma unroll
    for (int it = 0; it < 8; it++) {
        int idx = it * 256 + tid;                 // 64*32 = 2048
        int row = idx >> 5, c4 = idx & 31;
        float4 v = make_float4(0.f, 0.f, 0.f, 0.f);
        if (n0 + row < N_NODES) v = __ldg(nsrc + (size_t)(n0 + row) * 32 + c4);
        cvt_store(sAhi, sAlo, row * KP1 + c4 * 4, v);
    }
    const float4* asrc = (const float4*)g_agg;
    #pragma unroll
    for (int it = 0; it < 10; it++) {
        int idx = it * 256 + tid;                 // 64*40 = 2560
        int row = idx / 40, c4 = idx % 40;
        float4 v = make_float4(0.f, 0.f, 0.f, 0.f);
        if (n0 + row < N_NODES) v = asrc[(size_t)(n0 + row) * 40 + c4];
        cvt_store(sAhi, sAlo, row * KP1 + 128 + c4 * 4, v);
    }
    __syncthreads();

    const int lane = tid & 31;
    const int wid  = tid >> 5;        // 0..7
    const int wm   = wid >> 2;        // 0..1 (32 rows each)
    const int wn   = wid & 3;         // 0..3 (32 cols each)
    const int qr   = lane >> 2;
    const int qk   = 2 * (lane & 3);
    const int nbase = wn * 32;

    const int mrow = ((lane >> 3) & 1) * 8 + (lane & 7);
    const int kof  = (lane >> 4) * 8;
    const uint32_t sbase = smem_u32(smu);
    const uint32_t aHi0 = sbase + ((wm * 32 + mrow) * KP1 + kof) * 2;
    const uint32_t aHi1 = aHi0 + 16 * KP1 * 2;
    const uint32_t aLo0 = aHi0 + MROWS * KP1 * 2;
    const uint32_t aLo1 = aHi1 + MROWS * KP1 * 2;

    const uint4* wp1 = (const uint4*)g_w1p;
    const uint4* wp2 = (const uint4*)g_w2p;
    const uint4* wpn = (const uint4*)g_wnp;
    uint4 B0[4], B1[4];

    // =================== GEMM 1: [nodes|agg] @ Wcat^T (K=288) ===============
    float acc[2][4][4];
    #pragma unroll
    for (int mf = 0; mf < 2; mf++)
        #pragma unroll
        for (int nf = 0; nf < 4; nf++)
            #pragma unroll
            for (int i = 0; i < 4; i++) acc[mf][nf][i] = 0.f;

    load_bp(wp1, 0, wn, lane, B0);
    #pragma unroll 1
    for (int ks = 0; ks < KS1; ks += 2) {
        load_bp(wp1, ks + 1, wn, lane, B1);
        mma_step_lm(acc, aHi0 + ks * 32, aHi1 + ks * 32,
                    aLo0 + ks * 32, aLo1 + ks * 32, B0);
        if (ks + 2 < KS1) load_bp(wp1, ks + 2, wn, lane, B0);
        mma_step_lm(acc, aHi0 + (ks + 1) * 32, aHi1 + (ks + 1) * 32,
                    aLo0 + (ks + 1) * 32, aLo1 + (ks + 1) * 32, B1);
    }

    load_bp(wp2, 0, wn, lane, B0);   // prefetch GEMM2 behind LN1 epilogue

    // ---- bias + relu ----
    float vals[2][4][4];
    #pragma unroll
    for (int mf = 0; mf < 2; mf++)
        #pragma unroll
        for (int nf = 0; nf < 4; nf++) {
            int c = nbase + nf * 8 + qk;
            vals[mf][nf][0] = fmaxf(acc[mf][nf][0] + sb1[c], 0.f);
            vals[mf][nf][1] = fmaxf(acc[mf][nf][1] + sb1[c + 1], 0.f);
            vals[mf][nf][2] = fmaxf(acc[mf][nf][2] + sb1[c], 0.f);
            vals[mf][nf][3] = fmaxf(acc[mf][nf][3] + sb1[c + 1], 0.f);
        }

    // ---- LN1 reductions ----
    #pragma unroll
    for (int mf = 0; mf < 2; mf++)
        #pragma unroll
        for (int h = 0; h < 2; h++) {
            float s = 0.f, q = 0.f;
            #pragma unroll
            for (int nf = 0; nf < 4; nf++) {
                float v0 = vals[mf][nf][2 * h], v1 = vals[mf][nf][2 * h + 1];
                s += v0 + v1; q += v0 * v0 + v1 * v1;
            }
            s += __shfl_xor_sync(0xffffffffu, s, 1);
            s += __shfl_xor_sync(0xffffffffu, s, 2);
            q += __shfl_xor_sync(0xffffffffu, q, 1);
            q += __shfl_xor_sync(0xffffffffu, q, 2);
            int r = wm * 32 + mf * 16 + h * 8 + qr;
            if ((lane & 3) == 0) { sredS[r][wn] = s; sredQ[r][wn] = q; }
        }
    __syncthreads();

    // ---- LN1 apply; write h into the agg columns of sA ----
    #pragma unroll
    for (int mf = 0; mf < 2; mf++)
        #pragma unroll
        for (int h = 0; h < 2; h++) {
            int r = wm * 32 + mf * 16 + h * 8 + qr;
            float S = sredS[r][0] + sredS[r][1] + sredS[r][2] + sredS[r][3];
            float Q = sredQ[r][0] + sredQ[r][1] + sredQ[r][2] + sredQ[r][3];
            float mu = S * (1.f / 128.f);
            float var = Q * (1.f / 128.f) - mu * mu;
            float rs = rsqrtf(var + LN_EPS);
            #pragma unroll
            for (int nf = 0; nf < 4; nf++) {
                int c = nbase + nf * 8 + qk;
                float y0 = (vals[mf][nf][2 * h] - mu) * rs * sg1[c] + sbe1[c];
                float y1 = (vals[mf][nf][2 * h + 1] - mu) * rs * sg1[c + 1] + sbe1[c + 1];
                uint16_t h0 = f2bf(y0), h1 = f2bf(y1);
                uint16_t l0 = f2bf(y0 - bf2f(h0)), l1 = f2bf(y1 - bf2f(h1));
                *(uint32_t*)(sAhi + r * KP1 + 128 + c) = ((uint32_t)h1 << 16) | h0;
                *(uint32_t*)(sAlo + r * KP1 + 128 + c) = ((uint32_t)l1 << 16) | l0;
            }
        }
    __syncthreads();

    // =================== GEMM 2: h @ W2^T (K=128) ===========================
    #pragma unroll
    for (int mf = 0; mf < 2; mf++)
        #pragma unroll
        for (int nf = 0; nf < 4; nf++)
            #pragma unroll
            for (int i = 0; i < 4; i++) acc[mf][nf][i] = 0.f;
    #pragma unroll 1
    for (int ks = 0; ks < KS2; ks += 2) {
        load_bp(wp2, ks + 1, wn, lane, B1);
        mma_step_lm(acc, aHi0 + 256 + ks * 32, aHi1 + 256 + ks * 32,
                    aLo0 + 256 + ks * 32, aLo1 + 256 + ks * 32, B0);
        if (ks + 2 < KS2) load_bp(wp2, ks + 2, wn, lane, B0);
        mma_step_lm(acc, aHi0 + 256 + (ks + 1) * 32, aHi1 + 256 + (ks + 1) * 32,
                    aLo0 + 256 + (ks + 1) * 32, aLo1 + 256 + (ks + 1) * 32, B1);
    }

    load_bp(wpn, 0, wn, lane, B0);   // prefetch GEMM3 behind LN2 epilogue

    // ---- bias + relu -> uvals ----
    float uvals[2][4][4];
    #pragma unroll
    for (int mf = 0; mf < 2; mf++)
        #pragma unroll
        for (int nf = 0; nf < 4; nf++) {
            int c = nbase + nf * 8 + qk;
            uvals[mf][nf][0] = fmaxf(acc[mf][nf][0] + sb2[c], 0.f);
            uvals[mf][nf][1] = fmaxf(acc[mf][nf][1] + sb2[c + 1], 0.f);
            uvals[mf][nf][2] = fmaxf(acc[mf][nf][2] + sb2[c], 0.f);
            uvals[mf][nf][3] = fmaxf(acc[mf][nf][3] + sb2[c + 1], 0.f);
        }

    // ---- LN2 ----
    __syncthreads();
    #pragma unroll
    for (int mf = 0; mf < 2; mf++)
        #pragma unroll
        for (int h = 0; h < 2; h++) {
            float s = 0.f, q = 0.f;
            #pragma unroll
            for (int nf = 0; nf < 4; nf++) {
                float v0 = uvals[mf][nf][2 * h], v1 = uvals[mf][nf][2 * h + 1];
                s += v0 + v1; q += v0 * v0 + v1 * v1;
            }
            s += __shfl_xor_sync(0xffffffffu, s, 1);
            s += __shfl_xor_sync(0xffffffffu, s, 2);
            q += __shfl_xor_sync(0xffffffffu, q, 1);
            q += __shfl_xor_sync(0xffffffffu, q, 2);
            int r = wm * 32 + mf * 16 + h * 8 + qr;
            if ((lane & 3) == 0) { sredS[r][wn] = s; sredQ[r][wn] = q; }
        }
    __syncthreads();

    #pragma unroll
    for (int mf = 0; mf < 2; mf++)
        #pragma unroll
        for (int h = 0; h < 2; h++) {
            int r = wm * 32 + mf * 16 + h * 8 + qr;
            float S = sredS[r][0] + sredS[r][1] + sredS[r][2] + sredS[r][3];
            float Q = sredQ[r][0] + sredQ[r][1] + sredQ[r][2] + sredQ[r][3];
            float mu = S * (1.f / 128.f);
            float var = Q * (1.f / 128.f) - mu * mu;
            float rs = rsqrtf(var + LN_EPS);
            #pragma unroll
            for (int nf = 0; nf < 4; nf++) {
                int c = nbase + nf * 8 + qk;
                uvals[mf][nf][2 * h]     = (uvals[mf][nf][2 * h] - mu) * rs * sg2[c] + sbe2[c];
                uvals[mf][nf][2 * h + 1] = (uvals[mf][nf][2 * h + 1] - mu) * rs * sg2[c + 1] + sbe2[c + 1];
            }
        }
    __syncthreads();

    // =================== GEMM 3: nodes @ Wn^T (K=128) =======================
    #pragma unroll
    for (int mf = 0; mf < 2; mf++)
        #pragma unroll
        for (int nf = 0; nf < 4; nf++)
            #pragma unroll
            for (int i = 0; i < 4; i++) acc[mf][nf][i] = 0.f;
    #pragma unroll 1
    for (int ks = 0; ks < KS2; ks += 2) {
        load_bp(wpn, ks + 1, wn, lane, B1);
        mma_step_lm(acc, aHi0 + ks * 32, aHi1 + ks * 32,
                    aLo0 + ks * 32, aLo1 + ks * 32, B0);
        if (ks + 2 < KS2) load_bp(wpn, ks + 2, wn, lane, B0);
        mma_step_lm(acc, aHi0 + (ks + 1) * 32, aHi1 + (ks + 1) * 32,
                    aLo0 + (ks + 1) * 32, aLo1 + (ks + 1) * 32, B1);
    }

    // ---- v = acc + u; final LN ----
    #pragma unroll
    for (int mf = 0; mf < 2; mf++)
        #pragma unroll
        for (int nf = 0; nf < 4; nf++)
            #pragma unroll
            for (int i = 0; i < 4; i++)
                uvals[mf][nf][i] += acc[mf][nf][i];

    #pragma unroll
    for (int mf = 0; mf < 2; mf++)
        #pragma unroll
        for (int h = 0; h < 2; h++) {
            float s = 0.f, q = 0.f;
            #pragma unroll
            for (int nf = 0; nf < 4; nf++) {
                float v0 = uvals[mf][nf][2 * h], v1 = uvals[mf][nf][2 * h + 1];
                s += v0 + v1; q += v0 * v0 + v1 * v1;
            }
            s += __shfl_xor_sync(0xffffffffu, s, 1);
            s += __shfl_xor_sync(0xffffffffu, s, 2);
            q += __shfl_xor_sync(0xffffffffu, q, 1);
            q += __shfl_xor_sync(0xffffffffu, q, 2);
            int r = wm * 32 + mf * 16 + h * 8 + qr;
            if ((lane & 3) == 0) { sredS[r][wn] = s; sredQ[r][wn] = q; }
        }
    __syncthreads();

    #pragma unroll
    for (int mf = 0; mf < 2; mf++)
        #pragma unroll
        for (int h = 0; h < 2; h++) {
            int r = wm * 32 + mf * 16 + h * 8 + qr;
            int node = n0 + r;
            if (node >= N_NODES) continue;
            float S = sredS[r][0] + sredS[r][1] + sredS[r][2] + sredS[r][3];
            float Q = sredQ[r][0] + sredQ[r][1] + sredQ[r][2] + sredQ[r][3];
            float mu = S * (1.f / 128.f);
            float var = Q * (1.f / 128.f) - mu * mu;
            float rs = rsqrtf(var + LN_EPS);
            #pragma unroll
            for (int nf = 0; nf < 4; nf++) {
                int c = nbase + nf * 8 + qk;
                float2 o;
                o.x = (uvals[mf][nf][2 * h] - mu) * rs * sgf[c] + sbef[c];
                o.y = (uvals[mf][nf][2 * h + 1] - mu) * rs * sgf[c + 1] + sbef[c + 1];
                *(float2*)(out + (size_t)node * D + c) = o;
            }
        }
}

// --------------------------- launch -----------------------------------------
extern "C" void kernel_launch(void* const* d_in, const int* in_sizes, int n_in,
                              void* d_out, int out_size) {
    const float* nodes     = (const float*)d_in[0];
    const void*  eidx      = d_in[1];
    const float* edge_attr = (const float*)d_in[2];
    const float* Wm        = (const float*)d_in[3];
    const float* Wn        = (const float*)d_in[4];
    const float* W1        = (const float*)d_in[5];
    const float* b1        = (const float*)d_in[6];
    const float* g1        = (const float*)d_in[7];
    const float* be1       = (const float*)d_in[8];
    const float* W2        = (const float*)d_in[9];
    const float* b2        = (const float*)d_in[10];
    const float* g2        = (const float*)d_in[11];
    const float* be2       = (const float*)d_in[12];
    const float* gf        = (const float*)d_in[13];
    const float* bef       = (const float*)d_in[14];
    float* out = (float*)d_out;

    const int smem = MROWS * KP1 * 2 * (int)sizeof(uint16_t);   // 75776
    cudaFuncSetAttribute(node_phase_kernel, cudaFuncAttributeMaxDynamicSharedMemorySize, smem);

    csr_build_kernel<<<CSRB, 256>>>(eidx, W1, Wm, W2, Wn);                   // 1
    pull_kernel<<<(N_NODES + 7) / 8, 256>>>(                                 // 2
        (const float4*)nodes, (const float4*)edge_attr);
    node_phase_kernel<<<NGRP, 256, smem>>>(nodes, b1, g1, be1,               // 3
                                           b2, g2, be2, gf, bef, out);
}

// round 14
// speedup vs baseline: 1.2136x; 1.0026x over previous
#include <cuda_runtime.h>
#include <cuda_bf16.h>
#include <cstdint>

// ---------------------------------------------------------------------------
// LinearMessagePassingLayer — GB300 sm_103a, round 14.
//   csr:   persistent, 3 grid barriers (atomic chunk-base alloc, NO global scan);
//          P0 also does weight fuse+pack; (sender,eid) packed int2
//   pull:  CSR gather-sum (x4 unroll), single int2 index load per edge
//   node:  fused MLP, M=64 tiles, 256 thr, 2 blocks/SM
//   GEMMs: mma.sync m16n8k16 bf16, 3-term hi/lo split (~6e-6 rel err).
// ---------------------------------------------------------------------------

#define N_NODES 100000
#define N_EDGES 800000
#define D       128
#define ED      32
#define AD      160
#define LN_EPS  1e-5f
#define NB_SCAN ((N_NODES + 255) / 256)   // 391

#define KS1   18
#define KP1   296
#define KS2   8
#define MROWS 64
#define NGRP  ((N_NODES + MROWS - 1) / MROWS)   // 1563
#define CSRB  592

// --------------------------- device scratch -------------------------------
__device__ uint4    g_w1p[KS1 * 16 * 32];
__device__ uint4    g_w2p[KS2 * 16 * 32];
__device__ uint4    g_wnp[KS2 * 16 * 32];
__device__ float    g_agg[(size_t)N_NODES * AD];
__device__ int      g_sr[2 * N_EDGES];
__device__ int      g_cnt[N_NODES];            // counts -> offsets -> cursors -> ends
__device__ int      g_off[N_NODES];            // segment starts
__device__ int2     g_se[N_EDGES];             // (sender, edge id) by receiver-segment
__device__ unsigned g_bar;
__device__ int      g_tot;

// --------------------------- helpers ---------------------------------------
__device__ __forceinline__ uint16_t f2bf(float x) {
    __nv_bfloat16 h = __float2bfloat16(x);
    return *reinterpret_cast<uint16_t*>(&h);
}
__device__ __forceinline__ float bf2f(uint16_t b) {
    __nv_bfloat16 h = *reinterpret_cast<__nv_bfloat16*>(&b);
    return __bfloat162float(h);
}

__device__ __forceinline__ uint32_t smem_u32(const void* p) {
    uint32_t a;
    asm("{ .reg .u64 t; cvta.to.shared.u64 t, %1; cvt.u32.u64 %0, t; }"
        : "=r"(a) : "l"(p));
    return a;
}

__device__ __forceinline__ void mma_bf16(float (&c)[4], const uint32_t (&a)[4],
                                         uint32_t b0, uint32_t b1) {
    asm volatile(
        "mma.sync.aligned.m16n8k16.row.col.f32.bf16.bf16.f32 "
        "{%0,%1,%2,%3},{%4,%5,%6,%7},{%8,%9},{%0,%1,%2,%3};\n"
        : "+f"(c[0]), "+f"(c[1]), "+f"(c[2]), "+f"(c[3])
        : "r"(a[0]), "r"(a[1]), "r"(a[2]), "r"(a[3]), "r"(b0), "r"(b1));
}

__device__ __forceinline__ void ldsm_x4(uint32_t (&a)[4], uint32_t addr) {
    asm volatile("ldmatrix.sync.aligned.m8n8.x4.shared.b16 {%0,%1,%2,%3}, [%4];"
                 : "=r"(a[0]), "=r"(a[1]), "=r"(a[2]), "=r"(a[3]) : "r"(addr));
}

__device__ __forceinline__ void cvt_store(uint16_t* hi, uint16_t* lo, int off, float4 v) {
    uint16_t h0 = f2bf(v.x), h1 = f2bf(v.y), h2 = f2bf(v.z), h3 = f2bf(v.w);
    uint16_t l0 = f2bf(v.x - bf2f(h0)), l1 = f2bf(v.y - bf2f(h1));
    uint16_t l2 = f2bf(v.z - bf2f(h2)), l3 = f2bf(v.w - bf2f(h3));
    *(uint32_t*)(hi + off)     = ((uint32_t)h1 << 16) | h0;
    *(uint32_t*)(hi + off + 2) = ((uint32_t)h3 << 16) | h2;
    *(uint32_t*)(lo + off)     = ((uint32_t)l1 << 16) | l0;
    *(uint32_t*)(lo + off + 2) = ((uint32_t)l3 << 16) | l2;
}

__device__ __forceinline__ void mma_step_lm(float (&acc)[2][4][4],
                                            uint32_t aHi0, uint32_t aHi1,
                                            uint32_t aLo0, uint32_t aLo1,
                                            const uint4 (&B)[4]) {
    uint32_t ah0[4], ah1[4], al0[4], al1[4];
    ldsm_x4(ah0, aHi0);
    ldsm_x4(ah1, aHi1);
    ldsm_x4(al0, aLo0);
    ldsm_x4(al1, aLo1);
#pragma unroll
    for (int nf = 0; nf < 4; nf++) {
        mma_bf16(acc[0][nf], ah0, B[nf].x, B[nf].y);
        mma_bf16(acc[0][nf], ah0, B[nf].z, B[nf].w);
        mma_bf16(acc[0][nf], al0, B[nf].x, B[nf].y);
        mma_bf16(acc[1][nf], ah1, B[nf].x, B[nf].y);
        mma_bf16(acc[1][nf], ah1, B[nf].z, B[nf].w);
        mma_bf16(acc[1][nf], al1, B[nf].x, B[nf].y);
    }
}

__device__ __forceinline__ void load_bp(const uint4* __restrict__ wp, int ks,
                                        int wn, int lane, uint4 (&B)[4]) {
#pragma unroll
    for (int nf = 0; nf < 4; nf++)
        B[nf] = __ldg(wp + ((size_t)ks * 16 + wn * 4 + nf) * 32 + lane);
}

__device__ __forceinline__ uint4 pack_frag(float v0, float v1, float v2, float v3) {
    uint16_t h0 = f2bf(v0), h1 = f2bf(v1), h2 = f2bf(v2), h3 = f2bf(v3);
    uint16_t l0 = f2bf(v0 - bf2f(h0)), l1 = f2bf(v1 - bf2f(h1));
    uint16_t l2 = f2bf(v2 - bf2f(h2)), l3 = f2bf(v3 - bf2f(h3));
    uint4 r;
    r.x = ((uint32_t)h1 << 16) | h0;
    r.y = ((uint32_t)h3 << 16) | h2;
    r.z = ((uint32_t)l1 << 16) | l0;
    r.w = ((uint32_t)l3 << 16) | l2;
    return r;
}

// --------------------------- CSR build + weight prep (persistent) ----------
__device__ __forceinline__ void grid_bar(unsigned target) {
    __syncthreads();
    if (threadIdx.x == 0) {
        __threadfence();
        atomicAdd(&g_bar, 1u);
        while (*(volatile unsigned*)&g_bar < target) { }
        __threadfence();
    }
    __syncthreads();
}

__global__ void __launch_bounds__(256)
csr_build_kernel(const void* __restrict__ p,
                 const float* __restrict__ W1, const float* __restrict__ Wm,
                 const float* __restrict__ W2, const float* __restrict__ Wn) {
    __shared__ int s[256];
    __shared__ int sh_base;
    __shared__ int anynz;
    __shared__ float sw[D];
    __shared__ float swf[AD];
    const int t   = threadIdx.x;
    const int gid = blockIdx.x * 256 + t;
    const int gs  = CSRB * 256;

    // ---- P0: zero counts + (blocks < 128) weight fuse + pack ----
    for (int i = gid; i < N_NODES; i += gs) g_cnt[i] = 0;
    if (blockIdx.x < D) {
        const int j = blockIdx.x;
        if (t < D) sw[t] = W1[j * (2 * D) + D + t];
        __syncthreads();
        if (t < AD) {
            float acc = 0.f;
            #pragma unroll 8
            for (int k = 0; k < D; k++)
                acc += sw[k] * __ldg(&Wm[k * AD + t]);
            swf[t] = acc;
        }
        __syncthreads();
        const int ngrp = j >> 3, qr = j & 7;
        if (t < KS1 * 4) {
            int ks = t >> 2, qkq = t & 3;
            int lane = qr * 4 + qkq;
            int k0 = ks * 16 + 2 * qkq;
            float v[4];
            #pragma unroll
            for (int jj = 0; jj < 4; jj++) {
                int k = k0 + (jj >> 1) * 8 + (jj & 1);
                v[jj] = (k < D) ? W1[j * (2 * D) + k] : swf[k - D];
            }
            g_w1p[ks * 512 + ngrp * 32 + lane] = pack_frag(v[0], v[1], v[2], v[3]);
        } else if (t < KS1 * 4 + KS2 * 4) {
            int tt = t - KS1 * 4;
            int ks = tt >> 2, qkq = tt & 3;
            int lane = qr * 4 + qkq;
            int k0 = ks * 16 + 2 * qkq;
            g_w2p[ks * 512 + ngrp * 32 + lane] =
                pack_frag(W2[j * D + k0], W2[j * D + k0 + 1],
                          W2[j * D + k0 + 8], W2[j * D + k0 + 9]);
        } else if (t < KS1 * 4 + 2 * KS2 * 4) {
            int tt = t - KS1 * 4 - KS2 * 4;
            int ks = tt >> 2, qkq = tt & 3;
            int lane = qr * 4 + qkq;
            int k0 = ks * 16 + 2 * qkq;
            g_wnp[ks * 512 + ngrp * 32 + lane] =
                pack_frag(Wn[j * D + k0], Wn[j * D + k0 + 1],
                          Wn[j * D + k0 + 8], Wn[j * D + k0 + 9]);
        }
    }
    grid_bar(1 * CSRB);

    // ---- P1: convert indices + histogram receivers (2x vectorized) ----
    if (t == 0) anynz = 0;
    __syncthreads();
    if (t < 64) {
        if (((const unsigned int*)p)[2 * t + 1] != 0u) atomicOr(&anynz, 1);
    }
    __syncthreads();
    const int is64 = (anynz == 0);
    for (int i0 = gid * 2; i0 < 2 * N_EDGES; i0 += gs * 2) {
        int v0, v1;
        if (is64) {
            longlong2 ll = __ldg((const longlong2*)((const char*)p + (size_t)i0 * 8));
            v0 = (int)ll.x; v1 = (int)ll.y;
        } else {
            int2 ii = __ldg((const int2*)((const char*)p + (size_t)i0 * 4));
            v0 = ii.x; v1 = ii.y;
        }
        g_sr[i0] = v0;
        g_sr[i0 + 1] = v1;
        if (i0 >= N_EDGES) {
            atomicAdd(&g_cnt[v0], 1);
            atomicAdd(&g_cnt[v1], 1);
        }
    }
    grid_bar(2 * CSRB);

    // ---- P2: per-chunk scan + atomic base allocation (order-free) ----
    for (int c = blockIdx.x; c < NB_SCAN; c += CSRB) {
        const int i = c * 256 + t;
        int v = (i < N_NODES) ? __ldcg(&g_cnt[i]) : 0;
        s[t] = v;
        __syncthreads();
        for (int o = 1; o < 256; o <<= 1) {
            int x = (t >= o) ? s[t - o] : 0;
            __syncthreads();
            s[t] += x;
            __syncthreads();
        }
        if (t == 255) sh_base = atomicAdd(&g_tot, s[255]);
        __syncthreads();
        if (i < N_NODES) {
            int off = sh_base + s[t] - v;   // exclusive within chunk + chunk base
            g_off[i] = off;
            g_cnt[i] = off;                  // cursor
        }
        __syncthreads();
    }
    grid_bar(3 * CSRB);

    // ---- P3: fill (packed int2: sender, edge id) ----
    #pragma unroll 4
    for (int e = gid; e < N_EDGES; e += gs) {
        int r = __ldcg(&g_sr[N_EDGES + e]);
        int pos = atomicAdd(&g_cnt[r], 1);
        g_se[pos] = make_int2(__ldcg(&g_sr[e]), e);
    }
}

// --------------------------- pull aggregation -------------------------------
__global__ void __launch_bounds__(256)
pull_kernel(const float4* __restrict__ nodes4, const float4* __restrict__ ea4) {
    int n = blockIdx.x * 8 + (threadIdx.x >> 5);
    if (n >= N_NODES) return;
    const int lane = threadIdx.x & 31;
    const int beg = g_off[n], end = g_cnt[n];   // cursor == segment end after fill
    float4 an = make_float4(0.f, 0.f, 0.f, 0.f);
    float4 ae = make_float4(0.f, 0.f, 0.f, 0.f);
    int i = beg;
    for (; i + 4 <= end; i += 4) {
        int2 se0 = __ldg(&g_se[i]),     se1 = __ldg(&g_se[i + 1]);
        int2 se2 = __ldg(&g_se[i + 2]), se3 = __ldg(&g_se[i + 3]);
        float4 v0 = __ldg(nodes4 + (size_t)se0.x * 32 + lane);
        float4 v1 = __ldg(nodes4 + (size_t)se1.x * 32 + lane);
        float4 v2 = __ldg(nodes4 + (size_t)se2.x * 32 + lane);
        float4 v3 = __ldg(nodes4 + (size_t)se3.x * 32 + lane);
        an.x += v0.x + v1.x + v2.x + v3.x;
        an.y += v0.y + v1.y + v2.y + v3.y;
        an.z += v0.z + v1.z + v2.z + v3.z;
        an.w += v0.w + v1.w + v2.w + v3.w;
        if (lane < 8) {
            float4 w0 = __ldg(ea4 + (size_t)se0.y * 8 + lane);
            float4 w1 = __ldg(ea4 + (size_t)se1.y * 8 + lane);
            float4 w2 = __ldg(ea4 + (size_t)se2.y * 8 + lane);
            float4 w3 = __ldg(ea4 + (size_t)se3.y * 8 + lane);
            ae.x += w0.x + w1.x + w2.x + w3.x;
            ae.y += w0.y + w1.y + w2.y + w3.y;
            ae.z += w0.z + w1.z + w2.z + w3.z;
            ae.w += w0.w + w1.w + w2.w + w3.w;
        }
    }
    for (; i < end; i++) {
        int2 se = __ldg(&g_se[i]);
        float4 v = __ldg(nodes4 + (size_t)se.x * 32 + lane);
        an.x += v.x; an.y += v.y; an.z += v.z; an.w += v.w;
        if (lane < 8) {
            float4 w = __ldg(ea4 + (size_t)se.y * 8 + lane);
            ae.x += w.x; ae.y += w.y; ae.z += w.z; ae.w += w.w;
        }
    }
    float4* dst = reinterpret_cast<float4*>(g_agg) + (size_t)n * 40;
    dst[lane] = an;
    if (lane < 8) dst[32 + lane] = ae;
}

// --------------------------- fused node phase (M=64, 2 blk/SM) --------------
__global__ void __launch_bounds__(256, 2)
node_phase_kernel(const float* __restrict__ nodes,
                  const float* __restrict__ b1,
                  const float* __restrict__ g1,
                  const float* __restrict__ be1,
                  const float* __restrict__ b2,
                  const float* __restrict__ g2,
                  const float* __restrict__ be2,
                  const float* __restrict__ gf,
                  const float* __restrict__ bef,
                  float* __restrict__ out) {
    extern __shared__ uint16_t smu[];
    uint16_t* sAhi = smu;
    uint16_t* sAlo = smu + MROWS * KP1;

    __shared__ float sb1[D], sg1[D], sbe1[D];
    __shared__ float sb2[D], sg2[D], sbe2[D], sgf[D], sbef[D];
    __shared__ float sredS[MROWS][4], sredQ[MROWS][4];

    const int tid = threadIdx.x;
    const int n0 = blockIdx.x * MROWS;
    if (blockIdx.x == 0 && tid == 0) { g_bar = 0u; g_tot = 0; }  // reset for next replay
    if (tid < D) {
        sb1[tid] = b1[tid]; sg1[tid] = g1[tid]; sbe1[tid] = be1[tid];
        sb2[tid] = b2[tid]; sg2[tid] = g2[tid]; sbe2[tid] = be2[tid];
        sgf[tid] = gf[tid]; sbef[tid] = bef[tid];
    }

    // ---- load + convert A = [nodes | agg] (64 rows) ----
    const float4* nsrc = (const float4*)nodes;
    #pragma unroll
    for (int it = 0; it < 8; it++) {
        int idx = it * 256 + tid;
        int row = idx >> 5, c4 = idx & 31;
        float4 v = make_float4(0.f, 0.f, 0.f, 0.f);
        if (n0 + row < N_NODES) v = __ldg(nsrc + (size_t)(n0 + row) * 32 + c4);
        cvt_store(sAhi, sAlo, row * KP1 + c4 * 4, v);
    }
    const float4* asrc = (const float4*)g_agg;
    #pragma unroll
    for (int it = 0; it < 10; it++) {
        int idx = it * 256 + tid;
        int row = idx / 40, c4 = idx % 40;
        float4 v = make_float4(0.f, 0.f, 0.f, 0.f);
        if (n0 + row < N_NODES) v = asrc[(size_t)(n0 + row) * 40 + c4];
        cvt_store(sAhi, sAlo, row * KP1 + 128 + c4 * 4, v);
    }
    __syncthreads();

    const int lane = tid & 31;
    const int wid  = tid >> 5;
    const int wm   = wid >> 2;
    const int wn   = wid & 3;
    const int qr   = lane >> 2;
    const int qk   = 2 * (lane & 3);
    const int nbase = wn * 32;

    const int mrow = ((lane >> 3) & 1) * 8 + (lane & 7);
    const int kof  = (lane >> 4) * 8;
    const uint32_t sbase = smem_u32(smu);
    const uint32_t aHi0 = sbase + ((wm * 32 + mrow) * KP1 + kof) * 2;
    const uint32_t aHi1 = aHi0 + 16 * KP1 * 2;
    const uint32_t aLo0 = aHi0 + MROWS * KP1 * 2;
    const uint32_t aLo1 = aHi1 + MROWS * KP1 * 2;

    const uint4* wp1 = (const uint4*)g_w1p;
    const uint4* wp2 = (const uint4*)g_w2p;
    const uint4* wpn = (const uint4*)g_wnp;
    uint4 B0[4], B1[4];

    // =================== GEMM 1: [nodes|agg] @ Wcat^T (K=288) ===============
    float acc[2][4][4];
    #pragma unroll
    for (int mf = 0; mf < 2; mf++)
        #pragma unroll
        for (int nf = 0; nf < 4; nf++)
            #pragma unroll
            for (int i = 0; i < 4; i++) acc[mf][nf][i] = 0.f;

    load_bp(wp1, 0, wn, lane, B0);
    #pragma unroll 1
    for (int ks = 0; ks < KS1; ks += 2) {
        load_bp(wp1, ks + 1, wn, lane, B1);
        mma_step_lm(acc, aHi0 + ks * 32, aHi1 + ks * 32,
                    aLo0 + ks * 32, aLo1 + ks * 32, B0);
        if (ks + 2 < KS1) load_bp(wp1, ks + 2, wn, lane, B0);
        mma_step_lm(acc, aHi0 + (ks + 1) * 32, aHi1 + (ks + 1) * 32,
                    aLo0 + (ks + 1) * 32, aLo1 + (ks + 1) * 32, B1);
    }

    load_bp(wp2, 0, wn, lane, B0);   // prefetch GEMM2 behind LN1 epilogue

    // ---- bias + relu ----
    float vals[2][4][4];
    #pragma unroll
    for (int mf = 0; mf < 2; mf++)
        #pragma unroll
        for (int nf = 0; nf < 4; nf++) {
            int c = nbase + nf * 8 + qk;
            vals[mf][nf][0] = fmaxf(acc[mf][nf][0] + sb1[c], 0.f);
            vals[mf][nf][1] = fmaxf(acc[mf][nf][1] + sb1[c + 1], 0.f);
            vals[mf][nf][2] = fmaxf(acc[mf][nf][2] + sb1[c], 0.f);
            vals[mf][nf][3] = fmaxf(acc[mf][nf][3] + sb1[c + 1], 0.f);
        }

    // ---- LN1 reductions ----
    #pragma unroll
    for (int mf = 0; mf < 2; mf++)
        #pragma unroll
        for (int h = 0; h < 2; h++) {
            float s = 0.f, q = 0.f;
            #pragma unroll
            for (int nf = 0; nf < 4; nf++) {
                float v0 = vals[mf][nf][2 * h], v1 = vals[mf][nf][2 * h + 1];
                s += v0 + v1; q += v0 * v0 + v1 * v1;
            }
            s += __shfl_xor_sync(0xffffffffu, s, 1);
            s += __shfl_xor_sync(0xffffffffu, s, 2);
            q += __shfl_xor_sync(0xffffffffu, q, 1);
            q += __shfl_xor_sync(0xffffffffu, q, 2);
            int r = wm * 32 + mf * 16 + h * 8 + qr;
            if ((lane & 3) == 0) { sredS[r][wn] = s; sredQ[r][wn] = q; }
        }
    __syncthreads();

    // ---- LN1 apply; write h into the agg columns of sA ----
    #pragma unroll
    for (int mf = 0; mf < 2; mf++)
        #pragma unroll
        for (int h = 0; h < 2; h++) {
            int r = wm * 32 + mf * 16 + h * 8 + qr;
            float S = sredS[r][0] + sredS[r][1] + sredS[r][2] + sredS[r][3];
            float Q = sredQ[r][0] + sredQ[r][1] + sredQ[r][2] + sredQ[r][3];
            float mu = S * (1.f / 128.f);
            float var = Q * (1.f / 128.f) - mu * mu;
            float rs = rsqrtf(var + LN_EPS);
            #pragma unroll
            for (int nf = 0; nf < 4; nf++) {
                int c = nbase + nf * 8 + qk;
                float y0 = (vals[mf][nf][2 * h] - mu) * rs * sg1[c] + sbe1[c];
                float y1 = (vals[mf][nf][2 * h + 1] - mu) * rs * sg1[c + 1] + sbe1[c + 1];
                uint16_t h0 = f2bf(y0), h1 = f2bf(y1);
                uint16_t l0 = f2bf(y0 - bf2f(h0)), l1 = f2bf(y1 - bf2f(h1));
                *(uint32_t*)(sAhi + r * KP1 + 128 + c) = ((uint32_t)h1 << 16) | h0;
                *(uint32_t*)(sAlo + r * KP1 + 128 + c) = ((uint32_t)l1 << 16) | l0;
            }
        }
    __syncthreads();

    // =================== GEMM 2: h @ W2^T (K=128) ===========================
    #pragma unroll
    for (int mf = 0; mf < 2; mf++)
        #pragma unroll
        for (int nf = 0; nf < 4; nf++)
            #pragma unroll
            for (int i = 0; i < 4; i++) acc[mf][nf][i] = 0.f;
    #pragma unroll 1
    for (int ks = 0; ks < KS2; ks += 2) {
        load_bp(wp2, ks + 1, wn, lane, B1);
        mma_step_lm(acc, aHi0 + 256 + ks * 32, aHi1 + 256 + ks * 32,
                    aLo0 + 256 + ks * 32, aLo1 + 256 + ks * 32, B0);
        if (ks + 2 < KS2) load_bp(wp2, ks + 2, wn, lane, B0);
        mma_step_lm(acc, aHi0 + 256 + (ks + 1) * 32, aHi1 + 256 + (ks + 1) * 32,
                    aLo0 + 256 + (ks + 1) * 32, aLo1 + 256 + (ks + 1) * 32, B1);
    }

    load_bp(wpn, 0, wn, lane, B0);   // prefetch GEMM3 behind LN2 epilogue

    // ---- bias + relu -> uvals ----
    float uvals[2][4][4];
    #pragma unroll
    for (int mf = 0; mf < 2; mf++)
        #pragma unroll
        for (int nf = 0; nf < 4; nf++) {
            int c = nbase + nf * 8 + qk;
            uvals[mf][nf][0] = fmaxf(acc[mf][nf][0] + sb2[c], 0.f);
            uvals[mf][nf][1] = fmaxf(acc[mf][nf][1] + sb2[c + 1], 0.f);
            uvals[mf][nf][2] = fmaxf(acc[mf][nf][2] + sb2[c], 0.f);
            uvals[mf][nf][3] = fmaxf(acc[mf][nf][3] + sb2[c + 1], 0.f);
        }

    // ---- LN2 ----
    __syncthreads();
    #pragma unroll
    for (int mf = 0; mf < 2; mf++)
        #pragma unroll
        for (int h = 0; h < 2; h++) {
            float s = 0.f, q = 0.f;
            #pragma unroll
            for (int nf = 0; nf < 4; nf++) {
                float v0 = uvals[mf][nf][2 * h], v1 = uvals[mf][nf][2 * h + 1];
                s += v0 + v1; q += v0 * v0 + v1 * v1;
            }
            s += __shfl_xor_sync(0xffffffffu, s, 1);
            s += __shfl_xor_sync(0xffffffffu, s, 2);
            q += __shfl_xor_sync(0xffffffffu, q, 1);
            q += __shfl_xor_sync(0xffffffffu, q, 2);
            int r = wm * 32 + mf * 16 + h * 8 + qr;
            if ((lane & 3) == 0) { sredS[r][wn] = s; sredQ[r][wn] = q; }
        }
    __syncthreads();

    #pragma unroll
    for (int mf = 0; mf < 2; mf++)
        #pragma unroll
        for (int h = 0; h < 2; h++) {
            int r = wm * 32 + mf * 16 + h * 8 + qr;
            float S = sredS[r][0] + sredS[r][1] + sredS[r][2] + sredS[r][3];
            float Q = sredQ[r][0] + sredQ[r][1] + sredQ[r][2] + sredQ[r][3];
            float mu = S * (1.f / 128.f);
            float var = Q * (1.f / 128.f) - mu * mu;
            float rs = rsqrtf(var + LN_EPS);
            #pragma unroll
            for (int nf = 0; nf < 4; nf++) {
                int c = nbase + nf * 8 + qk;
                uvals[mf][nf][2 * h]     = (uvals[mf][nf][2 * h] - mu) * rs * sg2[c] + sbe2[c];
                uvals[mf][nf][2 * h + 1] = (uvals[mf][nf][2 * h + 1] - mu) * rs * sg2[c + 1] + sbe2[c + 1];
            }
        }
    __syncthreads();

    // =================== GEMM 3: nodes @ Wn^T (K=128) =======================
    #pragma unroll
    for (int mf = 0; mf < 2; mf++)
        #pragma unroll
        for (int nf = 0; nf < 4; nf++)
            #pragma unroll
            for (int i = 0; i < 4; i++) acc[mf][nf][i] = 0.f;
    #pragma unroll 1
    for (int ks = 0; ks < KS2; ks += 2) {
        load_bp(wpn, ks + 1, wn, lane, B1);
        mma_step_lm(acc, aHi0 + ks * 32, aHi1 + ks * 32,
                    aLo0 + ks * 32, aLo1 + ks * 32, B0);
        if (ks + 2 < KS2) load_bp(wpn, ks + 2, wn, lane, B0);
        mma_step_lm(acc, aHi0 + (ks + 1) * 32, aHi1 + (ks + 1) * 32,
                    aLo0 + (ks + 1) * 32, aLo1 + (ks + 1) * 32, B1);
    }

    // ---- v = acc + u; final LN ----
    #pragma unroll
    for (int mf = 0; mf < 2; mf++)
        #pragma unroll
        for (int nf = 0; nf < 4; nf++)
            #pragma unroll
            for (int i = 0; i < 4; i++)
                uvals[mf][nf][i] += acc[mf][nf][i];

    #pragma unroll
    for (int mf = 0; mf < 2; mf++)
        #pragma unroll
        for (int h = 0; h < 2; h++) {
            float s = 0.f, q = 0.f;
            #pragma unroll
            for (int nf = 0; nf < 4; nf++) {
                float v0 = uvals[mf][nf][2 * h], v1 = uvals[mf][nf][2 * h + 1];
                s += v0 + v1; q += v0 * v0 + v1 * v1;
            }
            s += __shfl_xor_sync(0xffffffffu, s, 1);
            s += __shfl_xor_sync(0xffffffffu, s, 2);
            q += __shfl_xor_sync(0xffffffffu, q, 1);
            q += __shfl_xor_sync(0xffffffffu, q, 2);
            int r = wm * 32 + mf * 16 + h * 8 + qr;
            if ((lane & 3) == 0) { sredS[r][wn] = s; sredQ[r][wn] = q; }
        }
    __syncthreads();

    #pragma unroll
    for (int mf = 0; mf < 2; mf++)
        #pragma unroll
        for (int h = 0; h < 2; h++) {
            int r = wm * 32 + mf * 16 + h * 8 + qr;
            int node = n0 + r;
            if (node >= N_NODES) continue;
            float S = sredS[r][0] + sredS[r][1] + sredS[r][2] + sredS[r][3];
            float Q = sredQ[r][0] + sredQ[r][1] + sredQ[r][2] + sredQ[r][3];
            float mu = S * (1.f / 128.f);
            float var = Q * (1.f / 128.f) - mu * mu;
            float rs = rsqrtf(var + LN_EPS);
            #pragma unroll
            for (int nf = 0; nf < 4; nf++) {
                int c = nbase + nf * 8 + qk;
                float2 o;
                o.x = (uvals[mf][nf][2 * h] - mu) * rs * sgf[c] + sbef[c];
                o.y = (uvals[mf][nf][2 * h + 1] - mu) * rs * sgf[c + 1] + sbef[c + 1];
                *(float2*)(out + (size_t)node * D + c) = o;
            }
        }
}

// --------------------------- launch -----------------------------------------
extern "C" void kernel_launch(void* const* d_in, const int* in_sizes, int n_in,
                              void* d_out, int out_size) {
    const float* nodes     = (const float*)d_in[0];
    const void*  eidx      = d_in[1];
    const float* edge_attr = (const float*)d_in[2];
    const float* Wm        = (const float*)d_in[3];
    const float* Wn        = (const float*)d_in[4];
    const float* W1        = (const float*)d_in[5];
    const float* b1        = (const float*)d_in[6];
    const float* g1        = (const float*)d_in[7];
    const float* be1       = (const float*)d_in[8];
    const float* W2        = (const float*)d_in[9];
    const float* b2        = (const float*)d_in[10];
    const float* g2        = (const float*)d_in[11];
    const float* be2       = (const float*)d_in[12];
    const float* gf        = (const float*)d_in[13];
    const float* bef       = (const float*)d_in[14];
    float* out = (float*)d_out;

    const int smem = MROWS * KP1 * 2 * (int)sizeof(uint16_t);   // 75776
    cudaFuncSetAttribute(node_phase_kernel, cudaFuncAttributeMaxDynamicSharedMemorySize, smem);

    csr_build_kernel<<<CSRB, 256>>>(eidx, W1, Wm, W2, Wn);                   // 1
    pull_kernel<<<(N_NODES + 7) / 8, 256>>>(                                 // 2
        (const float4*)nodes, (const float4*)edge_attr);
    node_phase_kernel<<<NGRP, 256, smem>>>(nodes, b1, g1, be1,               // 3
                                           b2, g2, be2, gf, bef, out);
}